// round 9
// baseline (speedup 1.0000x reference)
#include <cuda_runtime.h>
#include <cuda_fp16.h>
#include <math.h>
#include <stdint.h>

// ---------------- problem constants ----------------
#define BATCH 2048
#define LD    100
#define DIM   128
#define L1O   97
#define L2O   92
#define L3O   85

// ---------------- scratch (device globals; allocation-free) ----------------
__device__ __half g_x  [BATCH * LD  * DIM];
__device__ __half g_h1 [BATCH * L1O * 128];
__device__ __half g_h2 [BATCH * L2O * 256];
__device__ __half g_dc [BATCH * L3O * 512];
__device__ __half g_att[BATCH * L3O * 512];
__device__ __half g_hf1[BATCH * 128];
__device__ __half g_hf2[BATCH * 256];
__device__ __half g_fnn[BATCH * 512];
__device__ __half g_pair[BATCH * 1024];
__device__ __half g_fh1[BATCH * 1024];
__device__ __half g_fh2[BATCH * 1024];
__device__ float  g_Am [BATCH * L3O * 512];
__device__ float  g_fatt[BATCH * 512];
__device__ float  g_fh3[BATCH * 512];
__device__ float  g_fwm1[128 * 7];
__device__ __half g_w1r[128 * 512];
__device__ __half g_w2r[256 * 768];
__device__ __half g_w3r[512 * 2048];
__device__ __half g_fwm2[256 * 128];
__device__ __half g_fwm3[512 * 256];
__device__ __half g_Wda[512 * 512];
__device__ __half g_Wfa[512 * 512];
__device__ __half g_Watt[512 * 512];
__device__ __half g_W1[1024 * 1024];
__device__ __half g_W2[1024 * 1024];
__device__ __half g_W3[512 * 1024];

// ---------------- helpers ----------------
__device__ __forceinline__ uint32_t smem_u32(const void* p) {
    uint32_t a;
    asm("{ .reg .u64 t; cvta.to.shared.u64 t, %1; cvt.u32.u64 %0, t; }"
        : "=r"(a) : "l"(p));
    return a;
}
__device__ __forceinline__ void ldm4(uint32_t* r, uint32_t saddr) {
    asm volatile("ldmatrix.sync.aligned.m8n8.x4.shared.b16 {%0,%1,%2,%3}, [%4];"
        : "=r"(r[0]), "=r"(r[1]), "=r"(r[2]), "=r"(r[3]) : "r"(saddr));
}
__device__ __forceinline__ void mma16816(float* d, const uint32_t* a,
                                         uint32_t b0, uint32_t b1) {
    asm volatile(
        "mma.sync.aligned.m16n8k16.row.col.f32.f16.f16.f32 "
        "{%0,%1,%2,%3}, {%4,%5,%6,%7}, {%8,%9}, {%0,%1,%2,%3};"
        : "+f"(d[0]), "+f"(d[1]), "+f"(d[2]), "+f"(d[3])
        : "r"(a[0]), "r"(a[1]), "r"(a[2]), "r"(a[3]), "r"(b0), "r"(b1));
}
#define CPA16(dst, src) \
    asm volatile("cp.async.cg.shared.global [%0], [%1], 16;" :: "r"(dst), "l"(src) : "memory")
#define CPCOMMIT() asm volatile("cp.async.commit_group;" ::: "memory")
template <int NW> __device__ __forceinline__ void cpwait() {
    asm volatile("cp.async.wait_group %0;" :: "n"(NW) : "memory");
}

// epilogue activation + store
template <int ACT, int OM>  // OM: 0 fp32, 1 fp16
__device__ __forceinline__ void epi_store(float vx, float vy, long rowb, int n,
                                          float* Cf, __half* Ch) {
    if (ACT == 1 || ACT == 3) {
        vx = fmaxf(vx, 0.f); vy = fmaxf(vy, 0.f);
    } else if (ACT == 2) {
        vx = vx > 0.f ? vx : 0.01f * vx;
        vy = vy > 0.f ? vy : 0.01f * vy;
    }
    if (OM == 0) *(float2*)(Cf + rowb + n) = make_float2(vx, vy);
    else         *(__half2*)(Ch + rowb + n) = __floats2half2_rn(vx, vy);
}

// ---------------- unified GEMM: CTA 128x128, 4 warps (2x2), warp 64x64 ----------------
// 2 CTAs/SM co-resident: per-stage sync/load bubbles of one CTA are hidden by the other.
#define ROWB   80u
#define UPLN   10240u            // 128 rows * 80B
#define USTG   20480u            // A + B planes
#define USMEM  (2 * 20480)       // 2 stages = 40 KB -> 2 CTAs/SM

template <int ACT, int OM>  // ACT: 0 none,1 relu,2 leaky,3 relu(bias+extra)
__global__ __launch_bounds__(128, 2)
void gemmU(const __half* __restrict__ A, const __half* __restrict__ W,
           const float* __restrict__ bias, const float* __restrict__ extra,
           float* __restrict__ Cf, __half* __restrict__ Ch,
           int N, int K, int Lout, long sOuter, long sInner, int rowdiv) {
    extern __shared__ char sm[];
    const uint32_t smb = smem_u32(sm);
    const int tid = threadIdx.x;           // 0..127
    const int wid = tid >> 5, lane = tid & 31;
    const int m0 = blockIdx.y * 128, n0 = blockIdx.x * 128;
    const int wm = wid >> 1, wn = wid & 1; // 2x2 warp grid, 64x64 tiles

    // loaders: thread = one row of A and one row of B; 32 halves (64B) per stage
    const int mrow = m0 + tid;
    const __half* aP = A + (long)(mrow / Lout) * sOuter + (long)(mrow % Lout) * sInner;
    const __half* bP = W + (long)(n0 + tid) * K;
    const uint32_t aDst = smb + (uint32_t)tid * ROWB;
    const uint32_t bDst = smb + UPLN + (uint32_t)tid * ROWB;

    const int laneR = lane & 15;
    const uint32_t laneC = (uint32_t)(lane >> 4) * 16u;
    const uint32_t aBase = smb + (uint32_t)(wm * 64 + laneR) * ROWB + laneC;
    const uint32_t bBase = smb + UPLN + (uint32_t)(wn * 64 + laneR) * ROWB + laneC;

    float acc[4][8][4];
#pragma unroll
    for (int i = 0; i < 4; i++)
#pragma unroll
        for (int j = 0; j < 8; j++)
#pragma unroll
            for (int k = 0; k < 4; k++) acc[i][j][k] = 0.f;

    const int T = K / 32;
    {
#pragma unroll
        for (int s = 0; s < 4; s++) {
            CPA16(aDst + s * 16u, aP + s * 8);
            CPA16(bDst + s * 16u, bP + s * 8);
        }
        CPCOMMIT();
    }

    for (int t = 0; t < T; ++t) {
        if (t + 1 < T) {
            const int k0 = (t + 1) * 32;
            const uint32_t sb = (uint32_t)((t + 1) & 1) * USTG;
#pragma unroll
            for (int s = 0; s < 4; s++) {
                CPA16(aDst + sb + s * 16u, aP + k0 + s * 8);
                CPA16(bDst + sb + s * 16u, bP + k0 + s * 8);
            }
            CPCOMMIT();
            cpwait<1>();
        } else {
            cpwait<0>();
        }
        __syncthreads();

        const uint32_t soff = (uint32_t)(t & 1) * USTG;
#pragma unroll
        for (int j = 0; j < 2; j++) {
            const uint32_t ja = soff + (uint32_t)j * 32u;
            uint32_t af[4][4], bf[4][4];
#pragma unroll
            for (int mt = 0; mt < 4; mt++)
                ldm4(af[mt], aBase + ja + (uint32_t)mt * (16u * ROWB));
#pragma unroll
            for (int nt = 0; nt < 4; nt++)
                ldm4(bf[nt], bBase + ja + (uint32_t)nt * (16u * ROWB));
#pragma unroll
            for (int nt = 0; nt < 4; nt++)
#pragma unroll
                for (int mt = 0; mt < 4; mt++) {
                    mma16816(acc[mt][2 * nt],     af[mt], bf[nt][0], bf[nt][2]);
                    mma16816(acc[mt][2 * nt + 1], af[mt], bf[nt][1], bf[nt][3]);
                }
        }
        __syncthreads();
    }

    const int lr2 = lane >> 2;
    const int lc2 = (lane & 3) * 2;
#pragma unroll
    for (int mt = 0; mt < 4; mt++) {
#pragma unroll
        for (int h = 0; h < 2; h++) {
            const long m = (long)m0 + wm * 64 + mt * 16 + h * 8 + lr2;
            const long rowb = m * (long)N;
            const float* erow = (ACT == 3) ? (extra + (long)(m / rowdiv) * N) : nullptr;
#pragma unroll
            for (int nt2 = 0; nt2 < 8; nt2++) {
                const int n = n0 + wn * 64 + nt2 * 8 + lc2;
                float vx = acc[mt][nt2][2 * h]     + bias[n];
                float vy = acc[mt][nt2][2 * h + 1] + bias[n + 1];
                if (ACT == 3) {
                    float2 e = *(const float2*)(erow + n);
                    vx += e.x; vy += e.y;
                }
                epi_store<ACT, OM>(vx, vy, rowb, n, Cf, Ch);
            }
        }
    }
}

// ---------------- prep / glue kernels ----------------
__global__ void embed_h(const int* __restrict__ drug, const float* __restrict__ emb,
                        __half* __restrict__ x) {
    int idx = blockIdx.x * blockDim.x + threadIdx.x;
    const int total = BATCH * LD * (DIM / 4);
    if (idx >= total) return;
    int d4 = idx & 31;
    int bl = idx >> 5;
    int tok = drug[bl];
    float4 v = ((const float4*)emb)[(size_t)tok * 32 + d4];
    size_t pos = (size_t)bl * 128 + d4 * 4;
    *(__half2*)(x + pos)     = __floats2half2_rn(v.x, v.y);
    *(__half2*)(x + pos + 2) = __floats2half2_rn(v.z, v.w);
}

__global__ void reorder_w_h(const float* __restrict__ w, __half* __restrict__ wr,
                            int O, int Ci, int Kw) {
    int idx = blockIdx.x * blockDim.x + threadIdx.x;
    int total = O * Ci * Kw;
    if (idx >= total) return;
    int o = idx / (Ci * Kw);
    int rr = idx - o * (Ci * Kw);
    int i = rr / Kw;
    int k = rr - i * Kw;
    wr[(size_t)o * Ci * Kw + k * Ci + i] = __float2half_rn(w[idx]);
}

__global__ void midtap_h(const float* __restrict__ w, __half* __restrict__ wr, int total) {
    int idx = blockIdx.x * blockDim.x + threadIdx.x;
    if (idx >= total) return;
    wr[idx] = __float2half_rn(w[idx * 3 + 1]);
}

__global__ void midtap_f32(const float* __restrict__ w, float* __restrict__ wr, int total) {
    int idx = blockIdx.x * blockDim.x + threadIdx.x;
    if (idx >= total) return;
    wr[idx] = w[idx * 3 + 1];
}

__global__ void conv_h(const float* __restrict__ w, __half* __restrict__ wr, int total) {
    int idx = blockIdx.x * blockDim.x + threadIdx.x;
    if (idx >= total) return;
    wr[idx] = __float2half_rn(w[idx]);
}

__global__ void feat1_k(const float* __restrict__ feat, const float* __restrict__ wm,
                        const float* __restrict__ bias, __half* __restrict__ o1) {
    int idx = blockIdx.x * blockDim.x + threadIdx.x;
    if (idx >= BATCH * 128) return;
    int b = idx >> 7, o = idx & 127;
    float s = bias[o];
#pragma unroll
    for (int i = 0; i < 7; i++) s = fmaf(feat[b * 7 + i], wm[o * 7 + i], s);
    o1[idx] = __float2half_rn(fmaxf(s, 0.f));
}

__global__ void reduce_k(const __half* __restrict__ dc, const float* __restrict__ Am,
                         const __half* __restrict__ fnn,
                         __half* __restrict__ pair) {
    int b = blockIdx.x;
    int c = threadIdx.x;
    const size_t base = (size_t)b * L3O * 512 + c;
    float mx = -1e30f, smv = 0.f;
#pragma unroll 5
    for (int l = 0; l < L3O; l++) {
        float a = Am[base + (size_t)l * 512];
        float d = __half2float(dc[base + (size_t)l * 512]);
        float sg = 1.f / (1.f + expf(-a));
        mx = fmaxf(mx, d * (0.5f + sg));
        smv += a;
    }
    float fsig = 1.f / (1.f + expf(-smv * (1.0f / L3O)));
    float vf = __half2float(fnn[(size_t)b * 512 + c]) * (0.5f + fsig);
    pair[(size_t)b * 1024 + c]       = __float2half_rn(mx);
    pair[(size_t)b * 1024 + 512 + c] = __float2half_rn(vf);
}

__global__ void final_k(const float* __restrict__ h3, const float* __restrict__ Wo,
                        const float* __restrict__ bo, float* __restrict__ out) {
    int b = blockIdx.x;
    int t = threadIdx.x;
    float s = 0.f;
#pragma unroll
    for (int c = t; c < 512; c += 128) s = fmaf(h3[(size_t)b * 512 + c], Wo[c], s);
#pragma unroll
    for (int o = 16; o > 0; o >>= 1) s += __shfl_down_sync(0xffffffffu, s, o);
    __shared__ float red[4];
    if ((t & 31) == 0) red[t >> 5] = s;
    __syncthreads();
    if (t == 0) out[b] = red[0] + red[1] + red[2] + red[3] + bo[0];
}

// ---------------- host launch ----------------
#define GADDR(p, sym) cudaGetSymbolAddress((void**)&p, sym)

extern "C" void kernel_launch(void* const* d_in, const int* in_sizes, int n_in,
                              void* d_out, int out_size) {
    const int*   drug    = (const int*)  d_in[0];
    const float* feature = (const float*)d_in[1];
    const float* emb     = (const float*)d_in[2];
    const float* dw1 = (const float*)d_in[3];  const float* db1 = (const float*)d_in[4];
    const float* dw2 = (const float*)d_in[5];  const float* db2 = (const float*)d_in[6];
    const float* dw3 = (const float*)d_in[7];  const float* db3 = (const float*)d_in[8];
    const float* fw1 = (const float*)d_in[9];  const float* fb1 = (const float*)d_in[10];
    const float* fw2 = (const float*)d_in[11]; const float* fb2 = (const float*)d_in[12];
    const float* fw3 = (const float*)d_in[13]; const float* fb3 = (const float*)d_in[14];
    const float* Wda = (const float*)d_in[15]; const float* bda = (const float*)d_in[16];
    const float* Wfa = (const float*)d_in[17]; const float* bfa = (const float*)d_in[18];
    const float* Watt= (const float*)d_in[19]; const float* batt= (const float*)d_in[20];
    const float* W1  = (const float*)d_in[21]; const float* b1  = (const float*)d_in[22];
    const float* W2  = (const float*)d_in[23]; const float* b2  = (const float*)d_in[24];
    const float* W3  = (const float*)d_in[25]; const float* b3  = (const float*)d_in[26];
    const float* Wo  = (const float*)d_in[27]; const float* bo  = (const float*)d_in[28];
    float* out = (float*)d_out;

    __half *x,*h1,*h2,*dc,*att,*hf1,*hf2,*fnn,*pair,*fh1,*fh2;
    __half *w1r,*w2r,*w3r,*fwm2,*fwm3,*WdaH,*WfaH,*WattH,*W1H,*W2H,*W3H;
    float *Am,*fatt,*fh3,*fwm1;
    GADDR(x, g_x); GADDR(h1, g_h1); GADDR(h2, g_h2);
    GADDR(dc, g_dc); GADDR(att, g_att);
    GADDR(hf1, g_hf1); GADDR(hf2, g_hf2); GADDR(fnn, g_fnn);
    GADDR(pair, g_pair); GADDR(fh1, g_fh1); GADDR(fh2, g_fh2);
    GADDR(w1r, g_w1r); GADDR(w2r, g_w2r); GADDR(w3r, g_w3r);
    GADDR(fwm2, g_fwm2); GADDR(fwm3, g_fwm3);
    GADDR(WdaH, g_Wda); GADDR(WfaH, g_Wfa); GADDR(WattH, g_Watt);
    GADDR(W1H, g_W1); GADDR(W2H, g_W2); GADDR(W3H, g_W3);
    GADDR(Am, g_Am); GADDR(fatt, g_fatt); GADDR(fh3, g_fh3); GADDR(fwm1, g_fwm1);

    cudaFuncSetAttribute(gemmU<0,0>, cudaFuncAttributeMaxDynamicSharedMemorySize, USMEM);
    cudaFuncSetAttribute(gemmU<1,1>, cudaFuncAttributeMaxDynamicSharedMemorySize, USMEM);
    cudaFuncSetAttribute(gemmU<2,1>, cudaFuncAttributeMaxDynamicSharedMemorySize, USMEM);
    cudaFuncSetAttribute(gemmU<2,0>, cudaFuncAttributeMaxDynamicSharedMemorySize, USMEM);
    cudaFuncSetAttribute(gemmU<3,1>, cudaFuncAttributeMaxDynamicSharedMemorySize, USMEM);

    // prep
    embed_h<<<(BATCH * LD * 32 + 255) / 256, 256>>>(drug, emb, x);
    reorder_w_h<<<(128 * 128 * 4 + 255) / 256, 256>>>(dw1, w1r, 128, 128, 4);
    reorder_w_h<<<(256 * 128 * 6 + 255) / 256, 256>>>(dw2, w2r, 256, 128, 6);
    reorder_w_h<<<(512 * 256 * 8 + 255) / 256, 256>>>(dw3, w3r, 512, 256, 8);
    midtap_f32<<<(128 * 7 + 255) / 256, 256>>>(fw1, fwm1, 128 * 7);

    // drug conv stack (implicit GEMM, relu)
    gemmU<1,1><<<dim3(1, (BATCH * L1O) / 128), 128, USMEM>>>(x, w1r, db1,
        nullptr, nullptr, h1, 128, 512, L1O, (long)LD * 128, 128L, 1);
    gemmU<1,1><<<dim3(2, (BATCH * L2O) / 128), 128, USMEM>>>(h1, w2r, db2,
        nullptr, nullptr, h2, 256, 768, L2O, (long)L1O * 128, 128L, 1);
    gemmU<1,1><<<dim3(4, (BATCH * L3O) / 128), 128, USMEM>>>(h2, w3r, db3,
        nullptr, nullptr, dc, 512, 2048, L3O, (long)L2O * 256, 256L, 1);

    // feature branch
    midtap_h<<<(256 * 128 + 255) / 256, 256>>>(fw2, fwm2, 256 * 128);
    midtap_h<<<(512 * 256 + 255) / 256, 256>>>(fw3, fwm3, 512 * 256);
    conv_h<<<(512 * 512 + 255) / 256, 256>>>(Wda, WdaH, 512 * 512);
    conv_h<<<(512 * 512 + 255) / 256, 256>>>(Wfa, WfaH, 512 * 512);
    conv_h<<<(512 * 512 + 255) / 256, 256>>>(Watt, WattH, 512 * 512);

    feat1_k<<<(BATCH * 128) / 256, 256>>>(feature, fwm1, fb1, hf1);
    gemmU<1,1><<<dim3(2, BATCH / 128), 128, USMEM>>>(hf1, fwm2, fb2,
        nullptr, nullptr, hf2, 256, 128, BATCH, 0L, 128L, 1);
    gemmU<1,1><<<dim3(4, BATCH / 128), 128, USMEM>>>(hf2, fwm3, fb3,
        nullptr, nullptr, fnn, 512, 256, BATCH, 0L, 256L, 1);
    gemmU<0,0><<<dim3(4, BATCH / 128), 128, USMEM>>>(fnn, WfaH, bfa,
        nullptr, fatt, nullptr, 512, 512, BATCH, 0L, 512L, 1);

    // s = relu(dc @ Wda^T + bda + fatt[b]) fused
    gemmU<3,1><<<dim3(4, (BATCH * L3O) / 128), 128, USMEM>>>(dc, WdaH, bda,
        fatt, nullptr, att, 512, 512, BATCH * L3O, 0L, 512L, L3O);

    // A = s @ Watt^T + batt (fp32 out)
    gemmU<0,0><<<dim3(4, (BATCH * L3O) / 128), 128, USMEM>>>(att, WattH, batt,
        nullptr, Am, nullptr, 512, 512, BATCH * L3O, 0L, 512L, 1);

    reduce_k<<<BATCH, 512>>>(dc, Am, fnn, pair);

    // FC head
    conv_h<<<(1024 * 1024 + 255) / 256, 256>>>(W1, W1H, 1024 * 1024);
    conv_h<<<(1024 * 1024 + 255) / 256, 256>>>(W2, W2H, 1024 * 1024);
    conv_h<<<(512 * 1024 + 255) / 256, 256>>>(W3, W3H, 512 * 1024);

    gemmU<2,1><<<dim3(8, BATCH / 128), 128, USMEM>>>(pair, W1H, b1,
        nullptr, nullptr, fh1, 1024, 1024, BATCH, 0L, 1024L, 1);
    gemmU<2,1><<<dim3(8, BATCH / 128), 128, USMEM>>>(fh1, W2H, b2,
        nullptr, nullptr, fh2, 1024, 1024, BATCH, 0L, 1024L, 1);
    gemmU<2,0><<<dim3(4, BATCH / 128), 128, USMEM>>>(fh2, W3H, b3,
        nullptr, fh3, nullptr, 512, 1024, BATCH, 0L, 1024L, 1);

    final_k<<<BATCH, 128>>>(fh3, Wo, bo, out);
}

// round 10
// speedup vs baseline: 1.1203x; 1.1203x over previous
#include <cuda_runtime.h>
#include <cuda_fp16.h>
#include <math.h>
#include <stdint.h>

// ---------------- problem constants ----------------
#define BATCH 2048
#define LD    100
#define DIM   128
#define L1O   97
#define L2O   92
#define L3O   85

// ---------------- scratch (device globals; allocation-free) ----------------
__device__ __half g_x  [BATCH * LD  * DIM];
__device__ __half g_h1 [BATCH * L1O * 128];
__device__ __half g_h2 [BATCH * L2O * 256];
__device__ __half g_dc [BATCH * L3O * 512];
__device__ __half g_att[BATCH * L3O * 512];
__device__ __half g_hf1[BATCH * 128];
__device__ __half g_hf2[BATCH * 256];
__device__ __half g_fnn[BATCH * 512];
__device__ __half g_pair[BATCH * 1024];
__device__ __half g_fh1[BATCH * 1024];
__device__ __half g_fh2[BATCH * 1024];
__device__ __half g_Am [BATCH * L3O * 512];
__device__ __half g_fatt[BATCH * 512];
__device__ __half g_fh3[BATCH * 512];
__device__ float  g_fwm1[128 * 7];
__device__ __half g_w1r[128 * 512];
__device__ __half g_w2r[256 * 768];
__device__ __half g_w3r[512 * 2048];
__device__ __half g_fwm2[256 * 128];
__device__ __half g_fwm3[512 * 256];
__device__ __half g_Wda[512 * 512];
__device__ __half g_Wfa[512 * 512];
__device__ __half g_Watt[512 * 512];
__device__ __half g_W1[1024 * 1024];
__device__ __half g_W2[1024 * 1024];
__device__ __half g_W3[512 * 1024];

// ---------------- helpers ----------------
__device__ __forceinline__ uint32_t smem_u32(const void* p) {
    uint32_t a;
    asm("{ .reg .u64 t; cvta.to.shared.u64 t, %1; cvt.u32.u64 %0, t; }"
        : "=r"(a) : "l"(p));
    return a;
}
__device__ __forceinline__ void ldm4(uint32_t* r, uint32_t saddr) {
    asm volatile("ldmatrix.sync.aligned.m8n8.x4.shared.b16 {%0,%1,%2,%3}, [%4];"
        : "=r"(r[0]), "=r"(r[1]), "=r"(r[2]), "=r"(r[3]) : "r"(saddr));
}
__device__ __forceinline__ void mma16816(float* d, const uint32_t* a,
                                         uint32_t b0, uint32_t b1) {
    asm volatile(
        "mma.sync.aligned.m16n8k16.row.col.f32.f16.f16.f32 "
        "{%0,%1,%2,%3}, {%4,%5,%6,%7}, {%8,%9}, {%0,%1,%2,%3};"
        : "+f"(d[0]), "+f"(d[1]), "+f"(d[2]), "+f"(d[3])
        : "r"(a[0]), "r"(a[1]), "r"(a[2]), "r"(a[3]), "r"(b0), "r"(b1));
}
#define CPA16(dst, src) \
    asm volatile("cp.async.cg.shared.global [%0], [%1], 16;" :: "r"(dst), "l"(src) : "memory")
#define CPCOMMIT() asm volatile("cp.async.commit_group;" ::: "memory")
template <int NW> __device__ __forceinline__ void cpwait() {
    asm volatile("cp.async.wait_group %0;" :: "n"(NW) : "memory");
}

// epilogue activation + store; OM: 0 = fp16 plain out, 1 = fp16 act out
template <int ACT>
__device__ __forceinline__ void epi_store(float vx, float vy, long rowb, int n,
                                          __half* C) {
    if (ACT == 1 || ACT == 3) {
        vx = fmaxf(vx, 0.f); vy = fmaxf(vy, 0.f);
    } else if (ACT == 2) {
        vx = vx > 0.f ? vx : 0.01f * vx;
        vy = vy > 0.f ? vy : 0.01f * vy;
    }
    *(__half2*)(C + rowb + n) = __floats2half2_rn(vx, vy);
}

// ---------------- big GEMM: CTA 256x128, 8 warps (4x2), warp 64x64, KT=64 ----------------
#define ROWB   144u              // 64 halves + 8 pad halves; conflict-free mod 128
#define APLN   36864u            // 256 rows * 144B
#define GSTG   55296u            // A(36864) + B(128*144=18432)
#define GSMEM  (2 * 55296)       // 110592 B

template <int ACT>  // ACT: 0 none,1 relu,2 leaky,3 relu(bias+extra)
__global__ __launch_bounds__(256, 1)
void gemm2(const __half* __restrict__ A, const __half* __restrict__ W,
           const float* __restrict__ bias, const __half* __restrict__ extra,
           __half* __restrict__ C,
           int N, int K, int Lout, long sOuter, long sInner, int rowdiv) {
    extern __shared__ char sm[];
    const uint32_t smb = smem_u32(sm);
    const int tid = threadIdx.x;
    const int wid = tid >> 5, lane = tid & 31;
    const int m0 = blockIdx.y * 256, n0 = blockIdx.x * 128;
    const int wm = wid >> 1, wn = wid & 1;

    const int mrow = m0 + tid;
    const __half* aP = A + (long)(mrow / Lout) * sOuter + (long)(mrow % Lout) * sInner;
    const int bseg = (tid & 1) * 4;
    const __half* bP = W + (long)(n0 + (tid >> 1)) * K;

    const uint32_t aDst = smb + (uint32_t)tid * ROWB;
    const uint32_t bDst = smb + APLN + (uint32_t)(tid >> 1) * ROWB + (uint32_t)bseg * 16u;

    const int laneR = lane & 15;
    const uint32_t laneC = (uint32_t)(lane >> 4) * 16u;
    const uint32_t aBase = smb + (uint32_t)(wm * 64 + laneR) * ROWB + laneC;
    const uint32_t bBase = smb + APLN + (uint32_t)(wn * 64 + laneR) * ROWB + laneC;

    float acc[4][8][4];
#pragma unroll
    for (int i = 0; i < 4; i++)
#pragma unroll
        for (int j = 0; j < 8; j++)
#pragma unroll
            for (int k = 0; k < 4; k++) acc[i][j][k] = 0.f;

    const int T = K / 64;
    {
#pragma unroll
        for (int s = 0; s < 8; s++) CPA16(aDst + s * 16u, aP + s * 8);
#pragma unroll
        for (int s = 0; s < 4; s++) CPA16(bDst + s * 16u, bP + (bseg + s) * 8);
        CPCOMMIT();
    }

    for (int t = 0; t < T; ++t) {
        if (t + 1 < T) {
            const int k0 = (t + 1) * 64;
            const uint32_t sb = (uint32_t)((t + 1) & 1) * GSTG;
#pragma unroll
            for (int s = 0; s < 8; s++) CPA16(aDst + sb + s * 16u, aP + k0 + s * 8);
#pragma unroll
            for (int s = 0; s < 4; s++) CPA16(bDst + sb + s * 16u, bP + k0 + (bseg + s) * 8);
            CPCOMMIT();
            cpwait<1>();
        } else {
            cpwait<0>();
        }
        __syncthreads();

        const uint32_t soff = (uint32_t)(t & 1) * GSTG;
#pragma unroll
        for (int j = 0; j < 4; j++) {          // four k16 steps
            const uint32_t ja = soff + (uint32_t)j * 32u;
            uint32_t af[4][4], bf[4][4];
#pragma unroll
            for (int mt = 0; mt < 4; mt++)
                ldm4(af[mt], aBase + ja + (uint32_t)mt * (16u * ROWB));
#pragma unroll
            for (int nt = 0; nt < 4; nt++)
                ldm4(bf[nt], bBase + ja + (uint32_t)nt * (16u * ROWB));
#pragma unroll
            for (int nt = 0; nt < 4; nt++)
#pragma unroll
                for (int mt = 0; mt < 4; mt++) {
                    mma16816(acc[mt][2 * nt],     af[mt], bf[nt][0], bf[nt][2]);
                    mma16816(acc[mt][2 * nt + 1], af[mt], bf[nt][1], bf[nt][3]);
                }
        }
        __syncthreads();
    }

    const int lr2 = lane >> 2;
    const int lc2 = (lane & 3) * 2;
#pragma unroll
    for (int mt = 0; mt < 4; mt++) {
#pragma unroll
        for (int h = 0; h < 2; h++) {
            const long m = (long)m0 + wm * 64 + mt * 16 + h * 8 + lr2;
            const long rowb = m * (long)N;
            const __half* erow = (ACT == 3) ? (extra + (long)(m / rowdiv) * N) : nullptr;
#pragma unroll
            for (int nt2 = 0; nt2 < 8; nt2++) {
                const int n = n0 + wn * 64 + nt2 * 8 + lc2;
                float vx = acc[mt][nt2][2 * h]     + bias[n];
                float vy = acc[mt][nt2][2 * h + 1] + bias[n + 1];
                if (ACT == 3) {
                    float2 e = __half22float2(*(const __half2*)(erow + n));
                    vx += e.x; vy += e.y;
                }
                epi_store<ACT>(vx, vy, rowb, n, C);
            }
        }
    }
}

// ---------------- small GEMM: CTA 128x128, 8 warps, warp 32x64, KT=64 ----------------
#define SPLN   18432u            // 128 rows * 144B
#define SSTG   36864u
#define SSMEM  (2 * 36864)

template <int ACT>
__global__ __launch_bounds__(256, 1)
void gemmS(const __half* __restrict__ A, const __half* __restrict__ W,
           const float* __restrict__ bias, const __half* __restrict__ extra,
           __half* __restrict__ C,
           int N, int K, int Lout, long sOuter, long sInner, int rowdiv) {
    extern __shared__ char sm[];
    const uint32_t smb = smem_u32(sm);
    const int tid = threadIdx.x;
    const int wid = tid >> 5, lane = tid & 31;
    const int m0 = blockIdx.y * 128, n0 = blockIdx.x * 128;
    const int wm = wid >> 1, wn = wid & 1;

    // loaders: 2 threads per row, each 32 halves (4 x 16B)
    const int lrow = tid >> 1;
    const int lseg = (tid & 1) * 4;
    const int mrow = m0 + lrow;
    const __half* aP = A + (long)(mrow / Lout) * sOuter + (long)(mrow % Lout) * sInner;
    const __half* bP = W + (long)(n0 + lrow) * K;
    const uint32_t aDst = smb + (uint32_t)lrow * ROWB + (uint32_t)lseg * 16u;
    const uint32_t bDst = smb + SPLN + (uint32_t)lrow * ROWB + (uint32_t)lseg * 16u;

    const int laneR = lane & 15;
    const uint32_t laneC = (uint32_t)(lane >> 4) * 16u;
    const uint32_t aBase = smb + (uint32_t)(wm * 32 + laneR) * ROWB + laneC;
    const uint32_t bBase = smb + SPLN + (uint32_t)(wn * 64 + laneR) * ROWB + laneC;

    float acc[2][8][4];
#pragma unroll
    for (int i = 0; i < 2; i++)
#pragma unroll
        for (int j = 0; j < 8; j++)
#pragma unroll
            for (int k = 0; k < 4; k++) acc[i][j][k] = 0.f;

    const int T = K / 64;
    {
#pragma unroll
        for (int s = 0; s < 4; s++) {
            CPA16(aDst + s * 16u, aP + (lseg + s) * 8);
            CPA16(bDst + s * 16u, bP + (lseg + s) * 8);
        }
        CPCOMMIT();
    }

    for (int t = 0; t < T; ++t) {
        if (t + 1 < T) {
            const int k0 = (t + 1) * 64;
            const uint32_t sb = (uint32_t)((t + 1) & 1) * SSTG;
#pragma unroll
            for (int s = 0; s < 4; s++) {
                CPA16(aDst + sb + s * 16u, aP + k0 + (lseg + s) * 8);
                CPA16(bDst + sb + s * 16u, bP + k0 + (lseg + s) * 8);
            }
            CPCOMMIT();
            cpwait<1>();
        } else {
            cpwait<0>();
        }
        __syncthreads();

        const uint32_t soff = (uint32_t)(t & 1) * SSTG;
#pragma unroll
        for (int j = 0; j < 4; j++) {
            const uint32_t ja = soff + (uint32_t)j * 32u;
            uint32_t af[2][4], bf[4][4];
#pragma unroll
            for (int mt = 0; mt < 2; mt++)
                ldm4(af[mt], aBase + ja + (uint32_t)mt * (16u * ROWB));
#pragma unroll
            for (int nt = 0; nt < 4; nt++)
                ldm4(bf[nt], bBase + ja + (uint32_t)nt * (16u * ROWB));
#pragma unroll
            for (int nt = 0; nt < 4; nt++)
#pragma unroll
                for (int mt = 0; mt < 2; mt++) {
                    mma16816(acc[mt][2 * nt],     af[mt], bf[nt][0], bf[nt][2]);
                    mma16816(acc[mt][2 * nt + 1], af[mt], bf[nt][1], bf[nt][3]);
                }
        }
        __syncthreads();
    }

    const int lr2 = lane >> 2;
    const int lc2 = (lane & 3) * 2;
#pragma unroll
    for (int mt = 0; mt < 2; mt++) {
#pragma unroll
        for (int h = 0; h < 2; h++) {
            const long m = (long)m0 + wm * 32 + mt * 16 + h * 8 + lr2;
            const long rowb = m * (long)N;
            const __half* erow = (ACT == 3) ? (extra + (long)(m / rowdiv) * N) : nullptr;
#pragma unroll
            for (int nt2 = 0; nt2 < 8; nt2++) {
                const int n = n0 + wn * 64 + nt2 * 8 + lc2;
                float vx = acc[mt][nt2][2 * h]     + bias[n];
                float vy = acc[mt][nt2][2 * h + 1] + bias[n + 1];
                if (ACT == 3) {
                    float2 e = __half22float2(*(const __half2*)(erow + n));
                    vx += e.x; vy += e.y;
                }
                epi_store<ACT>(vx, vy, rowb, n, C);
            }
        }
    }
}

// ---------------- prep / glue kernels ----------------
__global__ void embed_h(const int* __restrict__ drug, const float* __restrict__ emb,
                        __half* __restrict__ x) {
    int idx = blockIdx.x * blockDim.x + threadIdx.x;
    const int total = BATCH * LD * (DIM / 4);
    if (idx >= total) return;
    int d4 = idx & 31;
    int bl = idx >> 5;
    int tok = drug[bl];
    float4 v = ((const float4*)emb)[(size_t)tok * 32 + d4];
    size_t pos = (size_t)bl * 128 + d4 * 4;
    *(__half2*)(x + pos)     = __floats2half2_rn(v.x, v.y);
    *(__half2*)(x + pos + 2) = __floats2half2_rn(v.z, v.w);
}

__global__ void reorder_w_h(const float* __restrict__ w, __half* __restrict__ wr,
                            int O, int Ci, int Kw) {
    int idx = blockIdx.x * blockDim.x + threadIdx.x;
    int total = O * Ci * Kw;
    if (idx >= total) return;
    int o = idx / (Ci * Kw);
    int rr = idx - o * (Ci * Kw);
    int i = rr / Kw;
    int k = rr - i * Kw;
    wr[(size_t)o * Ci * Kw + k * Ci + i] = __float2half_rn(w[idx]);
}

__global__ void midtap_h(const float* __restrict__ w, __half* __restrict__ wr, int total) {
    int idx = blockIdx.x * blockDim.x + threadIdx.x;
    if (idx >= total) return;
    wr[idx] = __float2half_rn(w[idx * 3 + 1]);
}

__global__ void midtap_f32(const float* __restrict__ w, float* __restrict__ wr, int total) {
    int idx = blockIdx.x * blockDim.x + threadIdx.x;
    if (idx >= total) return;
    wr[idx] = w[idx * 3 + 1];
}

__global__ void conv_h(const float* __restrict__ w, __half* __restrict__ wr, int total) {
    int idx = blockIdx.x * blockDim.x + threadIdx.x;
    if (idx >= total) return;
    wr[idx] = __float2half_rn(w[idx]);
}

__global__ void feat1_k(const float* __restrict__ feat, const float* __restrict__ wm,
                        const float* __restrict__ bias, __half* __restrict__ o1) {
    int idx = blockIdx.x * blockDim.x + threadIdx.x;
    if (idx >= BATCH * 128) return;
    int b = idx >> 7, o = idx & 127;
    float s = bias[o];
#pragma unroll
    for (int i = 0; i < 7; i++) s = fmaf(feat[b * 7 + i], wm[o * 7 + i], s);
    o1[idx] = __float2half_rn(fmaxf(s, 0.f));
}

__global__ void reduce_k(const __half* __restrict__ dc, const __half* __restrict__ Am,
                         const __half* __restrict__ fnn,
                         __half* __restrict__ pair) {
    int b = blockIdx.x;
    int c = threadIdx.x;
    const size_t base = (size_t)b * L3O * 512 + c;
    float mx = -1e30f, smv = 0.f;
#pragma unroll 5
    for (int l = 0; l < L3O; l++) {
        float a = __half2float(Am[base + (size_t)l * 512]);
        float d = __half2float(dc[base + (size_t)l * 512]);
        float sg = 1.f / (1.f + expf(-a));
        mx = fmaxf(mx, d * (0.5f + sg));
        smv += a;
    }
    float fsig = 1.f / (1.f + expf(-smv * (1.0f / L3O)));
    float vf = __half2float(fnn[(size_t)b * 512 + c]) * (0.5f + fsig);
    pair[(size_t)b * 1024 + c]       = __float2half_rn(mx);
    pair[(size_t)b * 1024 + 512 + c] = __float2half_rn(vf);
}

__global__ void final_k(const __half* __restrict__ h3, const float* __restrict__ Wo,
                        const float* __restrict__ bo, float* __restrict__ out) {
    int b = blockIdx.x;
    int t = threadIdx.x;
    float s = 0.f;
#pragma unroll
    for (int c = t; c < 512; c += 128)
        s = fmaf(__half2float(h3[(size_t)b * 512 + c]), Wo[c], s);
#pragma unroll
    for (int o = 16; o > 0; o >>= 1) s += __shfl_down_sync(0xffffffffu, s, o);
    __shared__ float red[4];
    if ((t & 31) == 0) red[t >> 5] = s;
    __syncthreads();
    if (t == 0) out[b] = red[0] + red[1] + red[2] + red[3] + bo[0];
}

// ---------------- host launch ----------------
#define GADDR(p, sym) cudaGetSymbolAddress((void**)&p, sym)

extern "C" void kernel_launch(void* const* d_in, const int* in_sizes, int n_in,
                              void* d_out, int out_size) {
    const int*   drug    = (const int*)  d_in[0];
    const float* feature = (const float*)d_in[1];
    const float* emb     = (const float*)d_in[2];
    const float* dw1 = (const float*)d_in[3];  const float* db1 = (const float*)d_in[4];
    const float* dw2 = (const float*)d_in[5];  const float* db2 = (const float*)d_in[6];
    const float* dw3 = (const float*)d_in[7];  const float* db3 = (const float*)d_in[8];
    const float* fw1 = (const float*)d_in[9];  const float* fb1 = (const float*)d_in[10];
    const float* fw2 = (const float*)d_in[11]; const float* fb2 = (const float*)d_in[12];
    const float* fw3 = (const float*)d_in[13]; const float* fb3 = (const float*)d_in[14];
    const float* Wda = (const float*)d_in[15]; const float* bda = (const float*)d_in[16];
    const float* Wfa = (const float*)d_in[17]; const float* bfa = (const float*)d_in[18];
    const float* Watt= (const float*)d_in[19]; const float* batt= (const float*)d_in[20];
    const float* W1  = (const float*)d_in[21]; const float* b1  = (const float*)d_in[22];
    const float* W2  = (const float*)d_in[23]; const float* b2  = (const float*)d_in[24];
    const float* W3  = (const float*)d_in[25]; const float* b3  = (const float*)d_in[26];
    const float* Wo  = (const float*)d_in[27]; const float* bo  = (const float*)d_in[28];
    float* out = (float*)d_out;

    __half *x,*h1,*h2,*dc,*att,*hf1,*hf2,*fnn,*pair,*fh1,*fh2,*Am,*fatt,*fh3;
    __half *w1r,*w2r,*w3r,*fwm2,*fwm3,*WdaH,*WfaH,*WattH,*W1H,*W2H,*W3H;
    float *fwm1;
    GADDR(x, g_x); GADDR(h1, g_h1); GADDR(h2, g_h2);
    GADDR(dc, g_dc); GADDR(att, g_att);
    GADDR(hf1, g_hf1); GADDR(hf2, g_hf2); GADDR(fnn, g_fnn);
    GADDR(pair, g_pair); GADDR(fh1, g_fh1); GADDR(fh2, g_fh2);
    GADDR(Am, g_Am); GADDR(fatt, g_fatt); GADDR(fh3, g_fh3);
    GADDR(w1r, g_w1r); GADDR(w2r, g_w2r); GADDR(w3r, g_w3r);
    GADDR(fwm2, g_fwm2); GADDR(fwm3, g_fwm3);
    GADDR(WdaH, g_Wda); GADDR(WfaH, g_Wfa); GADDR(WattH, g_Watt);
    GADDR(W1H, g_W1); GADDR(W2H, g_W2); GADDR(W3H, g_W3);
    GADDR(fwm1, g_fwm1);

    cudaFuncSetAttribute(gemm2<0>, cudaFuncAttributeMaxDynamicSharedMemorySize, GSMEM);
    cudaFuncSetAttribute(gemm2<1>, cudaFuncAttributeMaxDynamicSharedMemorySize, GSMEM);
    cudaFuncSetAttribute(gemm2<3>, cudaFuncAttributeMaxDynamicSharedMemorySize, GSMEM);
    cudaFuncSetAttribute(gemmS<0>, cudaFuncAttributeMaxDynamicSharedMemorySize, SSMEM);
    cudaFuncSetAttribute(gemmS<1>, cudaFuncAttributeMaxDynamicSharedMemorySize, SSMEM);
    cudaFuncSetAttribute(gemmS<2>, cudaFuncAttributeMaxDynamicSharedMemorySize, SSMEM);

    // prep
    embed_h<<<(BATCH * LD * 32 + 255) / 256, 256>>>(drug, emb, x);
    reorder_w_h<<<(128 * 128 * 4 + 255) / 256, 256>>>(dw1, w1r, 128, 128, 4);
    reorder_w_h<<<(256 * 128 * 6 + 255) / 256, 256>>>(dw2, w2r, 256, 128, 6);
    reorder_w_h<<<(512 * 256 * 8 + 255) / 256, 256>>>(dw3, w3r, 512, 256, 8);
    midtap_f32<<<(128 * 7 + 255) / 256, 256>>>(fw1, fwm1, 128 * 7);

    // drug conv stack
    gemmS<1><<<dim3(1, (BATCH * L1O) / 128), 256, SSMEM>>>(x, w1r, db1,
        nullptr, h1, 128, 512, L1O, (long)LD * 128, 128L, 1);
    gemm2<1><<<dim3(2, (BATCH * L2O) / 256), 256, GSMEM>>>(h1, w2r, db2,
        nullptr, h2, 256, 768, L2O, (long)L1O * 128, 128L, 1);
    gemm2<1><<<dim3(4, (BATCH * L3O) / 256), 256, GSMEM>>>(h2, w3r, db3,
        nullptr, dc, 512, 2048, L3O, (long)L2O * 256, 256L, 1);

    // feature branch
    midtap_h<<<(256 * 128 + 255) / 256, 256>>>(fw2, fwm2, 256 * 128);
    midtap_h<<<(512 * 256 + 255) / 256, 256>>>(fw3, fwm3, 512 * 256);
    conv_h<<<(512 * 512 + 255) / 256, 256>>>(Wda, WdaH, 512 * 512);
    conv_h<<<(512 * 512 + 255) / 256, 256>>>(Wfa, WfaH, 512 * 512);
    conv_h<<<(512 * 512 + 255) / 256, 256>>>(Watt, WattH, 512 * 512);

    feat1_k<<<(BATCH * 128) / 256, 256>>>(feature, fwm1, fb1, hf1);
    gemmS<1><<<dim3(2, BATCH / 128), 256, SSMEM>>>(hf1, fwm2, fb2,
        nullptr, hf2, 256, 128, BATCH, 0L, 128L, 1);
    gemmS<1><<<dim3(4, BATCH / 128), 256, SSMEM>>>(hf2, fwm3, fb3,
        nullptr, fnn, 512, 256, BATCH, 0L, 256L, 1);
    gemmS<0><<<dim3(4, BATCH / 128), 256, SSMEM>>>(fnn, WfaH, bfa,
        nullptr, fatt, 512, 512, BATCH, 0L, 512L, 1);

    // s = relu(dc @ Wda^T + bda + fatt[b]) fused
    gemm2<3><<<dim3(4, (BATCH * L3O) / 256), 256, GSMEM>>>(dc, WdaH, bda,
        fatt, att, 512, 512, BATCH * L3O, 0L, 512L, L3O);

    // A = s @ Watt^T + batt
    gemm2<0><<<dim3(4, (BATCH * L3O) / 256), 256, GSMEM>>>(att, WattH, batt,
        nullptr, Am, 512, 512, BATCH * L3O, 0L, 512L, 1);

    reduce_k<<<BATCH, 512>>>(dc, Am, fnn, pair);

    // FC head
    conv_h<<<(1024 * 1024 + 255) / 256, 256>>>(W1, W1H, 1024 * 1024);
    conv_h<<<(1024 * 1024 + 255) / 256, 256>>>(W2, W2H, 1024 * 1024);
    conv_h<<<(512 * 1024 + 255) / 256, 256>>>(W3, W3H, 512 * 1024);

    gemmS<2><<<dim3(8, BATCH / 128), 256, SSMEM>>>(pair, W1H, b1,
        nullptr, fh1, 1024, 1024, BATCH, 0L, 1024L, 1);
    gemmS<2><<<dim3(8, BATCH / 128), 256, SSMEM>>>(fh1, W2H, b2,
        nullptr, fh2, 1024, 1024, BATCH, 0L, 1024L, 1);
    gemmS<2><<<dim3(4, BATCH / 128), 256, SSMEM>>>(fh2, W3H, b3,
        nullptr, fh3, 512, 1024, BATCH, 0L, 1024L, 1);

    final_k<<<BATCH, 128>>>(fh3, Wo, bo, out);
}

// round 11
// speedup vs baseline: 1.1338x; 1.0121x over previous
#include <cuda_runtime.h>
#include <cuda_fp16.h>
#include <math.h>
#include <stdint.h>

// ---------------- problem constants ----------------
#define BATCH 2048
#define LD    100
#define DIM   128
#define L1O   97
#define L2O   92
#define L3O   85

// ---------------- scratch (device globals; allocation-free) ----------------
__device__ __half g_x  [BATCH * LD  * DIM];
__device__ __half g_h1 [BATCH * L1O * 128];
__device__ __half g_h2 [BATCH * L2O * 256];
__device__ __half g_dc [BATCH * L3O * 512];
__device__ __half g_att[BATCH * L3O * 512];
__device__ __half g_hf1[BATCH * 128];
__device__ __half g_hf2[BATCH * 256];
__device__ __half g_fnn[BATCH * 512];
__device__ __half g_pair[BATCH * 1024];
__device__ __half g_fh1[BATCH * 1024];
__device__ __half g_fh2[BATCH * 1024];
__device__ __half g_Am [BATCH * L3O * 512];
__device__ __half g_fatt[BATCH * 512];
__device__ __half g_fh3[BATCH * 512];
__device__ float  g_fwm1[128 * 7];
__device__ __half g_w1r[128 * 512];
__device__ __half g_w2r[256 * 768];
__device__ __half g_w3r[512 * 2048];
__device__ __half g_fwm2[256 * 128];
__device__ __half g_fwm3[512 * 256];
__device__ __half g_Wda[512 * 512];
__device__ __half g_Wfa[512 * 512];
__device__ __half g_Watt[512 * 512];
__device__ __half g_W1[1024 * 1024];
__device__ __half g_W2[1024 * 1024];
__device__ __half g_W3[512 * 1024];

// ---------------- helpers ----------------
__device__ __forceinline__ uint32_t smem_u32(const void* p) {
    uint32_t a;
    asm("{ .reg .u64 t; cvta.to.shared.u64 t, %1; cvt.u32.u64 %0, t; }"
        : "=r"(a) : "l"(p));
    return a;
}
__device__ __forceinline__ void ldm4(uint32_t* r, uint32_t saddr) {
    asm volatile("ldmatrix.sync.aligned.m8n8.x4.shared.b16 {%0,%1,%2,%3}, [%4];"
        : "=r"(r[0]), "=r"(r[1]), "=r"(r[2]), "=r"(r[3]) : "r"(saddr));
}
__device__ __forceinline__ void mma16816(float* d, const uint32_t* a,
                                         uint32_t b0, uint32_t b1) {
    asm volatile(
        "mma.sync.aligned.m16n8k16.row.col.f32.f16.f16.f32 "
        "{%0,%1,%2,%3}, {%4,%5,%6,%7}, {%8,%9}, {%0,%1,%2,%3};"
        : "+f"(d[0]), "+f"(d[1]), "+f"(d[2]), "+f"(d[3])
        : "r"(a[0]), "r"(a[1]), "r"(a[2]), "r"(a[3]), "r"(b0), "r"(b1));
}
#define CPA16(dst, src) \
    asm volatile("cp.async.cg.shared.global [%0], [%1], 16;" :: "r"(dst), "l"(src) : "memory")
#define CPCOMMIT() asm volatile("cp.async.commit_group;" ::: "memory")
template <int NW> __device__ __forceinline__ void cpwait() {
    asm volatile("cp.async.wait_group %0;" :: "n"(NW) : "memory");
}

// epilogue activation + fp16 store
template <int ACT>
__device__ __forceinline__ void epi_store(float vx, float vy, long rowb, int n,
                                          __half* C) {
    if (ACT == 1 || ACT == 3) {
        vx = fmaxf(vx, 0.f); vy = fmaxf(vy, 0.f);
    } else if (ACT == 2) {
        vx = vx > 0.f ? vx : 0.01f * vx;
        vy = vy > 0.f ? vy : 0.01f * vy;
    }
    *(__half2*)(C + rowb + n) = __floats2half2_rn(vx, vy);
}

// ---------------- big GEMM: CTA 256x128, 8 warps (4x2), warp 64x64, KT=32, 3 stages ----------------
#define ROWB   80u
#define APLN   20480u            // 256 rows * 80B
#define GSTG   30720u            // A + B planes per stage
#define GSMEM  (3 * 30720)       // 3-stage pipeline (92160 B)

template <int ACT>  // 0 none,1 relu,2 leaky,3 relu(bias+extra)
__global__ __launch_bounds__(256, 1)
void gemm2(const __half* __restrict__ A, const __half* __restrict__ W,
           const float* __restrict__ bias, const __half* __restrict__ extra,
           __half* __restrict__ C,
           int N, int K, int Lout, long sOuter, long sInner, int rowdiv) {
    extern __shared__ char sm[];
    const uint32_t smb = smem_u32(sm);
    const int tid = threadIdx.x;
    const int wid = tid >> 5, lane = tid & 31;
    const int m0 = blockIdx.y * 256, n0 = blockIdx.x * 128;
    const int wm = wid >> 1, wn = wid & 1;

    const int mrow = m0 + tid;
    const __half* aP = A + (long)(mrow / Lout) * sOuter + (long)(mrow % Lout) * sInner;
    const int bseg = (tid & 1) * 2;
    const __half* bP = W + (long)(n0 + (tid >> 1)) * K;

    const uint32_t aDst = smb + (uint32_t)tid * ROWB;
    const uint32_t bDst = smb + APLN + (uint32_t)(tid >> 1) * ROWB + (uint32_t)bseg * 16u;

    const int laneR = lane & 15;
    const uint32_t laneC = (uint32_t)(lane >> 4) * 16u;
    const uint32_t aBase = smb + (uint32_t)(wm * 64 + laneR) * ROWB + laneC;
    const uint32_t bBase = smb + APLN + (uint32_t)(wn * 64 + laneR) * ROWB + laneC;

    float acc[4][8][4];
#pragma unroll
    for (int i = 0; i < 4; i++)
#pragma unroll
        for (int j = 0; j < 8; j++)
#pragma unroll
            for (int k = 0; k < 4; k++) acc[i][j][k] = 0.f;

    const int T = K / 32;

    // prologue: stages 0 and 1
    {
#pragma unroll
        for (int s = 0; s < 4; s++) CPA16(aDst + s * 16u, aP + s * 8);
#pragma unroll
        for (int s = 0; s < 2; s++) CPA16(bDst + s * 16u, bP + (bseg + s) * 8);
        CPCOMMIT();
    }
    if (T > 1) {
        const uint32_t sb = GSTG;
#pragma unroll
        for (int s = 0; s < 4; s++) CPA16(aDst + sb + s * 16u, aP + 32 + s * 8);
#pragma unroll
        for (int s = 0; s < 2; s++) CPA16(bDst + sb + s * 16u, bP + 32 + (bseg + s) * 8);
        CPCOMMIT();
    }

    int buf = 0;                        // t % 3
    int buf2 = (T > 2) ? 2 : 0;         // (t+2) % 3 tracker
    for (int t = 0; t < T; ++t) {
        if (t + 2 < T) {
            const int k0 = (t + 2) * 32;
            const uint32_t sb = (uint32_t)buf2 * GSTG;
#pragma unroll
            for (int s = 0; s < 4; s++) CPA16(aDst + sb + s * 16u, aP + k0 + s * 8);
#pragma unroll
            for (int s = 0; s < 2; s++) CPA16(bDst + sb + s * 16u, bP + k0 + (bseg + s) * 8);
            CPCOMMIT();
            cpwait<2>();
            if (++buf2 == 3) buf2 = 0;
        } else if (t + 1 < T) {
            cpwait<1>();
        } else {
            cpwait<0>();
        }
        __syncthreads();

        const uint32_t soff = (uint32_t)buf * GSTG;
#pragma unroll
        for (int j = 0; j < 2; j++) {
            const uint32_t ja = soff + (uint32_t)j * 32u;
            uint32_t af[4][4], bf[4][4];
#pragma unroll
            for (int mt = 0; mt < 4; mt++)
                ldm4(af[mt], aBase + ja + (uint32_t)mt * (16u * ROWB));
#pragma unroll
            for (int nt = 0; nt < 4; nt++)
                ldm4(bf[nt], bBase + ja + (uint32_t)nt * (16u * ROWB));
#pragma unroll
            for (int nt = 0; nt < 4; nt++)
#pragma unroll
                for (int mt = 0; mt < 4; mt++) {
                    mma16816(acc[mt][2 * nt],     af[mt], bf[nt][0], bf[nt][2]);
                    mma16816(acc[mt][2 * nt + 1], af[mt], bf[nt][1], bf[nt][3]);
                }
        }
        __syncthreads();
        if (++buf == 3) buf = 0;
    }

    const int lr2 = lane >> 2;
    const int lc2 = (lane & 3) * 2;
#pragma unroll
    for (int mt = 0; mt < 4; mt++) {
#pragma unroll
        for (int h = 0; h < 2; h++) {
            const long m = (long)m0 + wm * 64 + mt * 16 + h * 8 + lr2;
            const long rowb = m * (long)N;
            const __half* erow = (ACT == 3) ? (extra + (long)(m / rowdiv) * N) : nullptr;
#pragma unroll
            for (int nt2 = 0; nt2 < 8; nt2++) {
                const int n = n0 + wn * 64 + nt2 * 8 + lc2;
                float vx = acc[mt][nt2][2 * h]     + bias[n];
                float vy = acc[mt][nt2][2 * h + 1] + bias[n + 1];
                if (ACT == 3) {
                    float2 e = __half22float2(*(const __half2*)(erow + n));
                    vx += e.x; vy += e.y;
                }
                epi_store<ACT>(vx, vy, rowb, n, C);
            }
        }
    }
}

// ---------------- small GEMM: CTA 128x128, 8 warps, warp 32x64, KT=32, 3 stages ----------------
#define SPLN   10240u
#define SSTG   20480u
#define SSMEM  (3 * 20480)

template <int ACT>
__global__ __launch_bounds__(256, 1)
void gemmS(const __half* __restrict__ A, const __half* __restrict__ W,
           const float* __restrict__ bias, const __half* __restrict__ extra,
           __half* __restrict__ C,
           int N, int K, int Lout, long sOuter, long sInner, int rowdiv) {
    extern __shared__ char sm[];
    const uint32_t smb = smem_u32(sm);
    const int tid = threadIdx.x;
    const int wid = tid >> 5, lane = tid & 31;
    const int m0 = blockIdx.y * 128, n0 = blockIdx.x * 128;
    const int wm = wid >> 1, wn = wid & 1;

    const int lrow = tid >> 1;
    const int lc   = (tid & 1) * 16;
    const int mrow = m0 + lrow;
    const __half* aP = A + (long)(mrow / Lout) * sOuter + (long)(mrow % Lout) * sInner + lc;
    const __half* bP = W + (long)(n0 + lrow) * K + lc;
    const uint32_t rowDst = smb + (uint32_t)lrow * ROWB + (uint32_t)(tid & 1) * 32u;

    const int laneR = lane & 15;
    const uint32_t laneC = (uint32_t)(lane >> 4) * 16u;
    const uint32_t aBase = smb + (uint32_t)(wm * 32 + laneR) * ROWB + laneC;
    const uint32_t bBase = smb + SPLN + (uint32_t)(wn * 64 + laneR) * ROWB + laneC;

    float acc[2][8][4];
#pragma unroll
    for (int i = 0; i < 2; i++)
#pragma unroll
        for (int j = 0; j < 8; j++)
#pragma unroll
            for (int k = 0; k < 4; k++) acc[i][j][k] = 0.f;

    const int T = K / 32;

    {
#pragma unroll
        for (int s = 0; s < 2; s++) {
            CPA16(rowDst + s * 16u,        aP + s * 8);
            CPA16(rowDst + SPLN + s * 16u, bP + s * 8);
        }
        CPCOMMIT();
    }
    if (T > 1) {
        const uint32_t sb = SSTG;
#pragma unroll
        for (int s = 0; s < 2; s++) {
            CPA16(rowDst + sb + s * 16u,        aP + 32 + s * 8);
            CPA16(rowDst + sb + SPLN + s * 16u, bP + 32 + s * 8);
        }
        CPCOMMIT();
    }

    int buf = 0;
    int buf2 = (T > 2) ? 2 : 0;
    for (int t = 0; t < T; ++t) {
        if (t + 2 < T) {
            const int k0 = (t + 2) * 32;
            const uint32_t sb = (uint32_t)buf2 * SSTG;
#pragma unroll
            for (int s = 0; s < 2; s++) {
                CPA16(rowDst + sb + s * 16u,        aP + k0 + s * 8);
                CPA16(rowDst + sb + SPLN + s * 16u, bP + k0 + s * 8);
            }
            CPCOMMIT();
            cpwait<2>();
            if (++buf2 == 3) buf2 = 0;
        } else if (t + 1 < T) {
            cpwait<1>();
        } else {
            cpwait<0>();
        }
        __syncthreads();

        const uint32_t soff = (uint32_t)buf * SSTG;
#pragma unroll
        for (int j = 0; j < 2; j++) {
            const uint32_t ja = soff + (uint32_t)j * 32u;
            uint32_t af[2][4], bf[4][4];
#pragma unroll
            for (int mt = 0; mt < 2; mt++)
                ldm4(af[mt], aBase + ja + (uint32_t)mt * (16u * ROWB));
#pragma unroll
            for (int nt = 0; nt < 4; nt++)
                ldm4(bf[nt], bBase + ja + (uint32_t)nt * (16u * ROWB));
#pragma unroll
            for (int nt = 0; nt < 4; nt++)
#pragma unroll
                for (int mt = 0; mt < 2; mt++) {
                    mma16816(acc[mt][2 * nt],     af[mt], bf[nt][0], bf[nt][2]);
                    mma16816(acc[mt][2 * nt + 1], af[mt], bf[nt][1], bf[nt][3]);
                }
        }
        __syncthreads();
        if (++buf == 3) buf = 0;
    }

    const int lr2 = lane >> 2;
    const int lc2 = (lane & 3) * 2;
#pragma unroll
    for (int mt = 0; mt < 2; mt++) {
#pragma unroll
        for (int h = 0; h < 2; h++) {
            const long m = (long)m0 + wm * 32 + mt * 16 + h * 8 + lr2;
            const long rowb = m * (long)N;
            const __half* erow = (ACT == 3) ? (extra + (long)(m / rowdiv) * N) : nullptr;
#pragma unroll
            for (int nt2 = 0; nt2 < 8; nt2++) {
                const int n = n0 + wn * 64 + nt2 * 8 + lc2;
                float vx = acc[mt][nt2][2 * h]     + bias[n];
                float vy = acc[mt][nt2][2 * h + 1] + bias[n + 1];
                if (ACT == 3) {
                    float2 e = __half22float2(*(const __half2*)(erow + n));
                    vx += e.x; vy += e.y;
                }
                epi_store<ACT>(vx, vy, rowb, n, C);
            }
        }
    }
}

// ---------------- prep / glue kernels ----------------
__global__ void embed_h(const int* __restrict__ drug, const float* __restrict__ emb,
                        __half* __restrict__ x) {
    int idx = blockIdx.x * blockDim.x + threadIdx.x;
    const int total = BATCH * LD * (DIM / 4);
    if (idx >= total) return;
    int d4 = idx & 31;
    int bl = idx >> 5;
    int tok = drug[bl];
    float4 v = ((const float4*)emb)[(size_t)tok * 32 + d4];
    size_t pos = (size_t)bl * 128 + d4 * 4;
    *(__half2*)(x + pos)     = __floats2half2_rn(v.x, v.y);
    *(__half2*)(x + pos + 2) = __floats2half2_rn(v.z, v.w);
}

__global__ void reorder_w_h(const float* __restrict__ w, __half* __restrict__ wr,
                            int O, int Ci, int Kw) {
    int idx = blockIdx.x * blockDim.x + threadIdx.x;
    int total = O * Ci * Kw;
    if (idx >= total) return;
    int o = idx / (Ci * Kw);
    int rr = idx - o * (Ci * Kw);
    int i = rr / Kw;
    int k = rr - i * Kw;
    wr[(size_t)o * Ci * Kw + k * Ci + i] = __float2half_rn(w[idx]);
}

__global__ void midtap_h(const float* __restrict__ w, __half* __restrict__ wr, int total) {
    int idx = blockIdx.x * blockDim.x + threadIdx.x;
    if (idx >= total) return;
    wr[idx] = __float2half_rn(w[idx * 3 + 1]);
}

__global__ void midtap_f32(const float* __restrict__ w, float* __restrict__ wr, int total) {
    int idx = blockIdx.x * blockDim.x + threadIdx.x;
    if (idx >= total) return;
    wr[idx] = w[idx * 3 + 1];
}

__global__ void conv_h(const float* __restrict__ w, __half* __restrict__ wr, int total) {
    int idx = blockIdx.x * blockDim.x + threadIdx.x;
    if (idx >= total) return;
    wr[idx] = __float2half_rn(w[idx]);
}

__global__ void feat1_k(const float* __restrict__ feat, const float* __restrict__ wm,
                        const float* __restrict__ bias, __half* __restrict__ o1) {
    int idx = blockIdx.x * blockDim.x + threadIdx.x;
    if (idx >= BATCH * 128) return;
    int b = idx >> 7, o = idx & 127;
    float s = bias[o];
#pragma unroll
    for (int i = 0; i < 7; i++) s = fmaf(feat[b * 7 + i], wm[o * 7 + i], s);
    o1[idx] = __float2half_rn(fmaxf(s, 0.f));
}

__global__ void reduce_k(const __half* __restrict__ dc, const __half* __restrict__ Am,
                         const __half* __restrict__ fnn,
                         __half* __restrict__ pair) {
    int b = blockIdx.x;
    int c = threadIdx.x;
    const size_t base = (size_t)b * L3O * 512 + c;
    float mx = -1e30f, smv = 0.f;
#pragma unroll 5
    for (int l = 0; l < L3O; l++) {
        float a = __half2float(Am[base + (size_t)l * 512]);
        float d = __half2float(dc[base + (size_t)l * 512]);
        float sg = 1.f / (1.f + expf(-a));
        mx = fmaxf(mx, d * (0.5f + sg));
        smv += a;
    }
    float fsig = 1.f / (1.f + expf(-smv * (1.0f / L3O)));
    float vf = __half2float(fnn[(size_t)b * 512 + c]) * (0.5f + fsig);
    pair[(size_t)b * 1024 + c]       = __float2half_rn(mx);
    pair[(size_t)b * 1024 + 512 + c] = __float2half_rn(vf);
}

__global__ void final_k(const __half* __restrict__ h3, const float* __restrict__ Wo,
                        const float* __restrict__ bo, float* __restrict__ out) {
    int b = blockIdx.x;
    int t = threadIdx.x;
    float s = 0.f;
#pragma unroll
    for (int c = t; c < 512; c += 128)
        s = fmaf(__half2float(h3[(size_t)b * 512 + c]), Wo[c], s);
#pragma unroll
    for (int o = 16; o > 0; o >>= 1) s += __shfl_down_sync(0xffffffffu, s, o);
    __shared__ float red[4];
    if ((t & 31) == 0) red[t >> 5] = s;
    __syncthreads();
    if (t == 0) out[b] = red[0] + red[1] + red[2] + red[3] + bo[0];
}

// ---------------- host launch ----------------
#define GADDR(p, sym) cudaGetSymbolAddress((void**)&p, sym)

extern "C" void kernel_launch(void* const* d_in, const int* in_sizes, int n_in,
                              void* d_out, int out_size) {
    const int*   drug    = (const int*)  d_in[0];
    const float* feature = (const float*)d_in[1];
    const float* emb     = (const float*)d_in[2];
    const float* dw1 = (const float*)d_in[3];  const float* db1 = (const float*)d_in[4];
    const float* dw2 = (const float*)d_in[5];  const float* db2 = (const float*)d_in[6];
    const float* dw3 = (const float*)d_in[7];  const float* db3 = (const float*)d_in[8];
    const float* fw1 = (const float*)d_in[9];  const float* fb1 = (const float*)d_in[10];
    const float* fw2 = (const float*)d_in[11]; const float* fb2 = (const float*)d_in[12];
    const float* fw3 = (const float*)d_in[13]; const float* fb3 = (const float*)d_in[14];
    const float* Wda = (const float*)d_in[15]; const float* bda = (const float*)d_in[16];
    const float* Wfa = (const float*)d_in[17]; const float* bfa = (const float*)d_in[18];
    const float* Watt= (const float*)d_in[19]; const float* batt= (const float*)d_in[20];
    const float* W1  = (const float*)d_in[21]; const float* b1  = (const float*)d_in[22];
    const float* W2  = (const float*)d_in[23]; const float* b2  = (const float*)d_in[24];
    const float* W3  = (const float*)d_in[25]; const float* b3  = (const float*)d_in[26];
    const float* Wo  = (const float*)d_in[27]; const float* bo  = (const float*)d_in[28];
    float* out = (float*)d_out;

    __half *x,*h1,*h2,*dc,*att,*hf1,*hf2,*fnn,*pair,*fh1,*fh2,*Am,*fatt,*fh3;
    __half *w1r,*w2r,*w3r,*fwm2,*fwm3,*WdaH,*WfaH,*WattH,*W1H,*W2H,*W3H;
    float *fwm1;
    GADDR(x, g_x); GADDR(h1, g_h1); GADDR(h2, g_h2);
    GADDR(dc, g_dc); GADDR(att, g_att);
    GADDR(hf1, g_hf1); GADDR(hf2, g_hf2); GADDR(fnn, g_fnn);
    GADDR(pair, g_pair); GADDR(fh1, g_fh1); GADDR(fh2, g_fh2);
    GADDR(Am, g_Am); GADDR(fatt, g_fatt); GADDR(fh3, g_fh3);
    GADDR(w1r, g_w1r); GADDR(w2r, g_w2r); GADDR(w3r, g_w3r);
    GADDR(fwm2, g_fwm2); GADDR(fwm3, g_fwm3);
    GADDR(WdaH, g_Wda); GADDR(WfaH, g_Wfa); GADDR(WattH, g_Watt);
    GADDR(W1H, g_W1); GADDR(W2H, g_W2); GADDR(W3H, g_W3);
    GADDR(fwm1, g_fwm1);

    cudaFuncSetAttribute(gemm2<0>, cudaFuncAttributeMaxDynamicSharedMemorySize, GSMEM);
    cudaFuncSetAttribute(gemm2<1>, cudaFuncAttributeMaxDynamicSharedMemorySize, GSMEM);
    cudaFuncSetAttribute(gemm2<3>, cudaFuncAttributeMaxDynamicSharedMemorySize, GSMEM);
    cudaFuncSetAttribute(gemmS<0>, cudaFuncAttributeMaxDynamicSharedMemorySize, SSMEM);
    cudaFuncSetAttribute(gemmS<1>, cudaFuncAttributeMaxDynamicSharedMemorySize, SSMEM);
    cudaFuncSetAttribute(gemmS<2>, cudaFuncAttributeMaxDynamicSharedMemorySize, SSMEM);

    // prep
    embed_h<<<(BATCH * LD * 32 + 255) / 256, 256>>>(drug, emb, x);
    reorder_w_h<<<(128 * 128 * 4 + 255) / 256, 256>>>(dw1, w1r, 128, 128, 4);
    reorder_w_h<<<(256 * 128 * 6 + 255) / 256, 256>>>(dw2, w2r, 256, 128, 6);
    reorder_w_h<<<(512 * 256 * 8 + 255) / 256, 256>>>(dw3, w3r, 512, 256, 8);
    midtap_f32<<<(128 * 7 + 255) / 256, 256>>>(fw1, fwm1, 128 * 7);

    // drug conv stack
    gemmS<1><<<dim3(1, (BATCH * L1O) / 128), 256, SSMEM>>>(x, w1r, db1,
        nullptr, h1, 128, 512, L1O, (long)LD * 128, 128L, 1);
    gemm2<1><<<dim3(2, (BATCH * L2O) / 256), 256, GSMEM>>>(h1, w2r, db2,
        nullptr, h2, 256, 768, L2O, (long)L1O * 128, 128L, 1);
    gemm2<1><<<dim3(4, (BATCH * L3O) / 256), 256, GSMEM>>>(h2, w3r, db3,
        nullptr, dc, 512, 2048, L3O, (long)L2O * 256, 256L, 1);

    // feature branch
    midtap_h<<<(256 * 128 + 255) / 256, 256>>>(fw2, fwm2, 256 * 128);
    midtap_h<<<(512 * 256 + 255) / 256, 256>>>(fw3, fwm3, 512 * 256);
    conv_h<<<(512 * 512 + 255) / 256, 256>>>(Wda, WdaH, 512 * 512);
    conv_h<<<(512 * 512 + 255) / 256, 256>>>(Wfa, WfaH, 512 * 512);
    conv_h<<<(512 * 512 + 255) / 256, 256>>>(Watt, WattH, 512 * 512);

    feat1_k<<<(BATCH * 128) / 256, 256>>>(feature, fwm1, fb1, hf1);
    gemmS<1><<<dim3(2, BATCH / 128), 256, SSMEM>>>(hf1, fwm2, fb2,
        nullptr, hf2, 256, 128, BATCH, 0L, 128L, 1);
    gemmS<1><<<dim3(4, BATCH / 128), 256, SSMEM>>>(hf2, fwm3, fb3,
        nullptr, fnn, 512, 256, BATCH, 0L, 256L, 1);
    gemmS<0><<<dim3(4, BATCH / 128), 256, SSMEM>>>(fnn, WfaH, bfa,
        nullptr, fatt, 512, 512, BATCH, 0L, 512L, 1);

    // s = relu(dc @ Wda^T + bda + fatt[b]) fused
    gemm2<3><<<dim3(4, (BATCH * L3O) / 256), 256, GSMEM>>>(dc, WdaH, bda,
        fatt, att, 512, 512, BATCH * L3O, 0L, 512L, L3O);

    // A = s @ Watt^T + batt
    gemm2<0><<<dim3(4, (BATCH * L3O) / 256), 256, GSMEM>>>(att, WattH, batt,
        nullptr, Am, 512, 512, BATCH * L3O, 0L, 512L, 1);

    reduce_k<<<BATCH, 512>>>(dc, Am, fnn, pair);

    // FC head
    conv_h<<<(1024 * 1024 + 255) / 256, 256>>>(W1, W1H, 1024 * 1024);
    conv_h<<<(1024 * 1024 + 255) / 256, 256>>>(W2, W2H, 1024 * 1024);
    conv_h<<<(512 * 1024 + 255) / 256, 256>>>(W3, W3H, 512 * 1024);

    gemmS<2><<<dim3(8, BATCH / 128), 256, SSMEM>>>(pair, W1H, b1,
        nullptr, fh1, 1024, 1024, BATCH, 0L, 1024L, 1);
    gemmS<2><<<dim3(8, BATCH / 128), 256, SSMEM>>>(fh1, W2H, b2,
        nullptr, fh2, 1024, 1024, BATCH, 0L, 1024L, 1);
    gemmS<2><<<dim3(4, BATCH / 128), 256, SSMEM>>>(fh2, W3H, b3,
        nullptr, fh3, 512, 1024, BATCH, 0L, 1024L, 1);

    final_k<<<BATCH, 128>>>(fh3, Wo, bo, out);
}

// round 12
// speedup vs baseline: 1.1354x; 1.0014x over previous
#include <cuda_runtime.h>
#include <cuda_fp16.h>
#include <math.h>
#include <stdint.h>

// ---------------- problem constants ----------------
#define BATCH 2048
#define LD    100
#define DIM   128
#define L1O   97
#define L2O   92
#define L3O   85

// ---------------- scratch (device globals; allocation-free) ----------------
__device__ __half g_x  [BATCH * LD  * DIM];
__device__ __half g_h1 [BATCH * L1O * 128];
__device__ __half g_h2 [BATCH * L2O * 256];
__device__ __half g_dc [BATCH * L3O * 512];
__device__ __half g_att[BATCH * L3O * 512];
__device__ __half g_hf1[BATCH * 128];
__device__ __half g_hf2[BATCH * 256];
__device__ __half g_fnn[BATCH * 512];
__device__ __half g_pair[BATCH * 1024];
__device__ __half g_fh1[BATCH * 1024];
__device__ __half g_fh2[BATCH * 1024];
__device__ __half g_Am [BATCH * L3O * 512];
__device__ __half g_fatt[BATCH * 512];
__device__ __half g_fh3[BATCH * 512];
__device__ float  g_fwm1[128 * 7];
__device__ __half g_w1r[128 * 512];
__device__ __half g_w2r[256 * 768];
__device__ __half g_w3r[512 * 2048];
__device__ __half g_fwm2[256 * 128];
__device__ __half g_fwm3[512 * 256];
__device__ __half g_Wda[512 * 512];
__device__ __half g_Wfa[512 * 512];
__device__ __half g_Watt[512 * 512];
__device__ __half g_W1[1024 * 1024];
__device__ __half g_W2[1024 * 1024];
__device__ __half g_W3[512 * 1024];

// ---------------- helpers ----------------
__device__ __forceinline__ uint32_t smem_u32(const void* p) {
    uint32_t a;
    asm("{ .reg .u64 t; cvta.to.shared.u64 t, %1; cvt.u32.u64 %0, t; }"
        : "=r"(a) : "l"(p));
    return a;
}
__device__ __forceinline__ void ldm4(uint32_t* r, uint32_t saddr) {
    asm volatile("ldmatrix.sync.aligned.m8n8.x4.shared.b16 {%0,%1,%2,%3}, [%4];"
        : "=r"(r[0]), "=r"(r[1]), "=r"(r[2]), "=r"(r[3]) : "r"(saddr));
}
__device__ __forceinline__ void mma16816(float* d, const uint32_t* a,
                                         uint32_t b0, uint32_t b1) {
    asm volatile(
        "mma.sync.aligned.m16n8k16.row.col.f32.f16.f16.f32 "
        "{%0,%1,%2,%3}, {%4,%5,%6,%7}, {%8,%9}, {%0,%1,%2,%3};"
        : "+f"(d[0]), "+f"(d[1]), "+f"(d[2]), "+f"(d[3])
        : "r"(a[0]), "r"(a[1]), "r"(a[2]), "r"(a[3]), "r"(b0), "r"(b1));
}
#define CPA16(dst, src) \
    asm volatile("cp.async.cg.shared.global [%0], [%1], 16;" :: "r"(dst), "l"(src) : "memory")
#define CPCOMMIT() asm volatile("cp.async.commit_group;" ::: "memory")
template <int NW> __device__ __forceinline__ void cpwait() {
    asm volatile("cp.async.wait_group %0;" :: "n"(NW) : "memory");
}

template <int ACT>
__device__ __forceinline__ void epi_store(float vx, float vy, long rowb, int n,
                                          __half* C) {
    if (ACT == 1 || ACT == 3) {
        vx = fmaxf(vx, 0.f); vy = fmaxf(vy, 0.f);
    } else if (ACT == 2) {
        vx = vx > 0.f ? vx : 0.01f * vx;
        vy = vy > 0.f ? vy : 0.01f * vy;
    }
    *(__half2*)(C + rowb + n) = __floats2half2_rn(vx, vy);
}

#define ROWB   80u

// ---------------- wide GEMM: CTA 128(M)x256(N), 8 warps (2m x 4n), warp 64x64 ----------------
#define WAPLN  10240u            // A: 128 rows * 80B
#define WSTG   30720u            // A(10240) + B(256*80=20480)
#define WSMEM  (3 * 30720)

template <int ACT>  // 0 none,1 relu,2 leaky,3 relu(bias+extra)
__global__ __launch_bounds__(256, 1)
void gemmW(const __half* __restrict__ A, const __half* __restrict__ W,
           const float* __restrict__ bias, const __half* __restrict__ extra,
           __half* __restrict__ C,
           int N, int K, int Lout, long sOuter, long sInner, int rowdiv) {
    extern __shared__ char sm[];
    const uint32_t smb = smem_u32(sm);
    const int tid = threadIdx.x;
    const int wid = tid >> 5, lane = tid & 31;
    const int m0 = blockIdx.y * 128, n0 = blockIdx.x * 256;
    const int wm = wid >> 2, wn = wid & 3;

    // A loader: 2 threads per row (row = tid>>1, 16-half segment = tid&1)
    const int lrow = tid >> 1;
    const int lseg = tid & 1;
    const int mrow = m0 + lrow;
    const __half* aP = A + (long)(mrow / Lout) * sOuter + (long)(mrow % Lout) * sInner
                         + lseg * 16;
    const uint32_t aDst = smb + (uint32_t)lrow * ROWB + (uint32_t)lseg * 32u;
    // B loader: 1 thread per row (256 rows), 64B each
    const __half* bP = W + (long)(n0 + tid) * K;
    const uint32_t bDst = smb + WAPLN + (uint32_t)tid * ROWB;

    const int laneR = lane & 15;
    const uint32_t laneC = (uint32_t)(lane >> 4) * 16u;
    const uint32_t aBase = smb + (uint32_t)(wm * 64 + laneR) * ROWB + laneC;
    const uint32_t bBase = smb + WAPLN + (uint32_t)(wn * 64 + laneR) * ROWB + laneC;

    float acc[4][8][4];
#pragma unroll
    for (int i = 0; i < 4; i++)
#pragma unroll
        for (int j = 0; j < 8; j++)
#pragma unroll
            for (int k = 0; k < 4; k++) acc[i][j][k] = 0.f;

    const int T = K / 32;

    // prologue: stages 0 and 1
    {
#pragma unroll
        for (int s = 0; s < 2; s++) CPA16(aDst + s * 16u, aP + s * 8);
#pragma unroll
        for (int s = 0; s < 4; s++) CPA16(bDst + s * 16u, bP + s * 8);
        CPCOMMIT();
    }
    if (T > 1) {
#pragma unroll
        for (int s = 0; s < 2; s++) CPA16(aDst + WSTG + s * 16u, aP + 32 + s * 8);
#pragma unroll
        for (int s = 0; s < 4; s++) CPA16(bDst + WSTG + s * 16u, bP + 32 + s * 8);
        CPCOMMIT();
    }

    int buf = 0;
    int buf2 = (T > 2) ? 2 : 0;
    for (int t = 0; t < T; ++t) {
        if (t + 2 < T) {
            const int k0 = (t + 2) * 32;
            const uint32_t sb = (uint32_t)buf2 * WSTG;
#pragma unroll
            for (int s = 0; s < 2; s++) CPA16(aDst + sb + s * 16u, aP + k0 + s * 8);
#pragma unroll
            for (int s = 0; s < 4; s++) CPA16(bDst + sb + s * 16u, bP + k0 + s * 8);
            CPCOMMIT();
            cpwait<2>();
            if (++buf2 == 3) buf2 = 0;
        } else if (t + 1 < T) {
            cpwait<1>();
        } else {
            cpwait<0>();
        }
        __syncthreads();

        const uint32_t soff = (uint32_t)buf * WSTG;
#pragma unroll
        for (int j = 0; j < 2; j++) {
            const uint32_t ja = soff + (uint32_t)j * 32u;
            uint32_t af[4][4], bf[4][4];
#pragma unroll
            for (int mt = 0; mt < 4; mt++)
                ldm4(af[mt], aBase + ja + (uint32_t)mt * (16u * ROWB));
#pragma unroll
            for (int nt = 0; nt < 4; nt++)
                ldm4(bf[nt], bBase + ja + (uint32_t)nt * (16u * ROWB));
#pragma unroll
            for (int nt = 0; nt < 4; nt++)
#pragma unroll
                for (int mt = 0; mt < 4; mt++) {
                    mma16816(acc[mt][2 * nt],     af[mt], bf[nt][0], bf[nt][2]);
                    mma16816(acc[mt][2 * nt + 1], af[mt], bf[nt][1], bf[nt][3]);
                }
        }
        __syncthreads();
        if (++buf == 3) buf = 0;
    }

    const int lr2 = lane >> 2;
    const int lc2 = (lane & 3) * 2;
#pragma unroll
    for (int mt = 0; mt < 4; mt++) {
#pragma unroll
        for (int h = 0; h < 2; h++) {
            const long m = (long)m0 + wm * 64 + mt * 16 + h * 8 + lr2;
            const long rowb = m * (long)N;
            const __half* erow = (ACT == 3) ? (extra + (long)(m / rowdiv) * N) : nullptr;
#pragma unroll
            for (int nt2 = 0; nt2 < 8; nt2++) {
                const int n = n0 + wn * 64 + nt2 * 8 + lc2;
                float vx = acc[mt][nt2][2 * h]     + bias[n];
                float vy = acc[mt][nt2][2 * h + 1] + bias[n + 1];
                if (ACT == 3) {
                    float2 e = __half22float2(*(const __half2*)(erow + n));
                    vx += e.x; vy += e.y;
                }
                epi_store<ACT>(vx, vy, rowb, n, C);
            }
        }
    }
}

// ---------------- small GEMM: CTA 128x128, 8 warps, warp 32x64, KT=32, 3 stages ----------------
#define SPLN   10240u
#define SSTG   20480u
#define SSMEM  (3 * 20480)

template <int ACT>
__global__ __launch_bounds__(256, 1)
void gemmS(const __half* __restrict__ A, const __half* __restrict__ W,
           const float* __restrict__ bias, const __half* __restrict__ extra,
           __half* __restrict__ C,
           int N, int K, int Lout, long sOuter, long sInner, int rowdiv) {
    extern __shared__ char sm[];
    const uint32_t smb = smem_u32(sm);
    const int tid = threadIdx.x;
    const int wid = tid >> 5, lane = tid & 31;
    const int m0 = blockIdx.y * 128, n0 = blockIdx.x * 128;
    const int wm = wid >> 1, wn = wid & 1;

    const int lrow = tid >> 1;
    const int lc   = (tid & 1) * 16;
    const int mrow = m0 + lrow;
    const __half* aP = A + (long)(mrow / Lout) * sOuter + (long)(mrow % Lout) * sInner + lc;
    const __half* bP = W + (long)(n0 + lrow) * K + lc;
    const uint32_t rowDst = smb + (uint32_t)lrow * ROWB + (uint32_t)(tid & 1) * 32u;

    const int laneR = lane & 15;
    const uint32_t laneC = (uint32_t)(lane >> 4) * 16u;
    const uint32_t aBase = smb + (uint32_t)(wm * 32 + laneR) * ROWB + laneC;
    const uint32_t bBase = smb + SPLN + (uint32_t)(wn * 64 + laneR) * ROWB + laneC;

    float acc[2][8][4];
#pragma unroll
    for (int i = 0; i < 2; i++)
#pragma unroll
        for (int j = 0; j < 8; j++)
#pragma unroll
            for (int k = 0; k < 4; k++) acc[i][j][k] = 0.f;

    const int T = K / 32;

    {
#pragma unroll
        for (int s = 0; s < 2; s++) {
            CPA16(rowDst + s * 16u,        aP + s * 8);
            CPA16(rowDst + SPLN + s * 16u, bP + s * 8);
        }
        CPCOMMIT();
    }
    if (T > 1) {
#pragma unroll
        for (int s = 0; s < 2; s++) {
            CPA16(rowDst + SSTG + s * 16u,        aP + 32 + s * 8);
            CPA16(rowDst + SSTG + SPLN + s * 16u, bP + 32 + s * 8);
        }
        CPCOMMIT();
    }

    int buf = 0;
    int buf2 = (T > 2) ? 2 : 0;
    for (int t = 0; t < T; ++t) {
        if (t + 2 < T) {
            const int k0 = (t + 2) * 32;
            const uint32_t sb = (uint32_t)buf2 * SSTG;
#pragma unroll
            for (int s = 0; s < 2; s++) {
                CPA16(rowDst + sb + s * 16u,        aP + k0 + s * 8);
                CPA16(rowDst + sb + SPLN + s * 16u, bP + k0 + s * 8);
            }
            CPCOMMIT();
            cpwait<2>();
            if (++buf2 == 3) buf2 = 0;
        } else if (t + 1 < T) {
            cpwait<1>();
        } else {
            cpwait<0>();
        }
        __syncthreads();

        const uint32_t soff = (uint32_t)buf * SSTG;
#pragma unroll
        for (int j = 0; j < 2; j++) {
            const uint32_t ja = soff + (uint32_t)j * 32u;
            uint32_t af[2][4], bf[4][4];
#pragma unroll
            for (int mt = 0; mt < 2; mt++)
                ldm4(af[mt], aBase + ja + (uint32_t)mt * (16u * ROWB));
#pragma unroll
            for (int nt = 0; nt < 4; nt++)
                ldm4(bf[nt], bBase + ja + (uint32_t)nt * (16u * ROWB));
#pragma unroll
            for (int nt = 0; nt < 4; nt++)
#pragma unroll
                for (int mt = 0; mt < 2; mt++) {
                    mma16816(acc[mt][2 * nt],     af[mt], bf[nt][0], bf[nt][2]);
                    mma16816(acc[mt][2 * nt + 1], af[mt], bf[nt][1], bf[nt][3]);
                }
        }
        __syncthreads();
        if (++buf == 3) buf = 0;
    }

    const int lr2 = lane >> 2;
    const int lc2 = (lane & 3) * 2;
#pragma unroll
    for (int mt = 0; mt < 2; mt++) {
#pragma unroll
        for (int h = 0; h < 2; h++) {
            const long m = (long)m0 + wm * 32 + mt * 16 + h * 8 + lr2;
            const long rowb = m * (long)N;
            const __half* erow = (ACT == 3) ? (extra + (long)(m / rowdiv) * N) : nullptr;
#pragma unroll
            for (int nt2 = 0; nt2 < 8; nt2++) {
                const int n = n0 + wn * 64 + nt2 * 8 + lc2;
                float vx = acc[mt][nt2][2 * h]     + bias[n];
                float vy = acc[mt][nt2][2 * h + 1] + bias[n + 1];
                if (ACT == 3) {
                    float2 e = __half22float2(*(const __half2*)(erow + n));
                    vx += e.x; vy += e.y;
                }
                epi_store<ACT>(vx, vy, rowb, n, C);
            }
        }
    }
}

// ---------------- prep / glue kernels ----------------
__global__ void embed_h(const int* __restrict__ drug, const float* __restrict__ emb,
                        __half* __restrict__ x) {
    int idx = blockIdx.x * blockDim.x + threadIdx.x;
    const int total = BATCH * LD * (DIM / 4);
    if (idx >= total) return;
    int d4 = idx & 31;
    int bl = idx >> 5;
    int tok = drug[bl];
    float4 v = ((const float4*)emb)[(size_t)tok * 32 + d4];
    size_t pos = (size_t)bl * 128 + d4 * 4;
    *(__half2*)(x + pos)     = __floats2half2_rn(v.x, v.y);
    *(__half2*)(x + pos + 2) = __floats2half2_rn(v.z, v.w);
}

__global__ void reorder_w_h(const float* __restrict__ w, __half* __restrict__ wr,
                            int O, int Ci, int Kw) {
    int idx = blockIdx.x * blockDim.x + threadIdx.x;
    int total = O * Ci * Kw;
    if (idx >= total) return;
    int o = idx / (Ci * Kw);
    int rr = idx - o * (Ci * Kw);
    int i = rr / Kw;
    int k = rr - i * Kw;
    wr[(size_t)o * Ci * Kw + k * Ci + i] = __float2half_rn(w[idx]);
}

__global__ void midtap_h(const float* __restrict__ w, __half* __restrict__ wr, int total) {
    int idx = blockIdx.x * blockDim.x + threadIdx.x;
    if (idx >= total) return;
    wr[idx] = __float2half_rn(w[idx * 3 + 1]);
}

__global__ void midtap_f32(const float* __restrict__ w, float* __restrict__ wr, int total) {
    int idx = blockIdx.x * blockDim.x + threadIdx.x;
    if (idx >= total) return;
    wr[idx] = w[idx * 3 + 1];
}

__global__ void conv_h(const float* __restrict__ w, __half* __restrict__ wr, int total) {
    int idx = blockIdx.x * blockDim.x + threadIdx.x;
    if (idx >= total) return;
    wr[idx] = __float2half_rn(w[idx]);
}

__global__ void feat1_k(const float* __restrict__ feat, const float* __restrict__ wm,
                        const float* __restrict__ bias, __half* __restrict__ o1) {
    int idx = blockIdx.x * blockDim.x + threadIdx.x;
    if (idx >= BATCH * 128) return;
    int b = idx >> 7, o = idx & 127;
    float s = bias[o];
#pragma unroll
    for (int i = 0; i < 7; i++) s = fmaf(feat[b * 7 + i], wm[o * 7 + i], s);
    o1[idx] = __float2half_rn(fmaxf(s, 0.f));
}

__global__ void reduce_k(const __half* __restrict__ dc, const __half* __restrict__ Am,
                         const __half* __restrict__ fnn,
                         __half* __restrict__ pair) {
    int b = blockIdx.x;
    int c = threadIdx.x;
    const size_t base = (size_t)b * L3O * 512 + c;
    float mx = -1e30f, smv = 0.f;
#pragma unroll 5
    for (int l = 0; l < L3O; l++) {
        float a = __half2float(Am[base + (size_t)l * 512]);
        float d = __half2float(dc[base + (size_t)l * 512]);
        float sg = 1.f / (1.f + expf(-a));
        mx = fmaxf(mx, d * (0.5f + sg));
        smv += a;
    }
    float fsig = 1.f / (1.f + expf(-smv * (1.0f / L3O)));
    float vf = __half2float(fnn[(size_t)b * 512 + c]) * (0.5f + fsig);
    pair[(size_t)b * 1024 + c]       = __float2half_rn(mx);
    pair[(size_t)b * 1024 + 512 + c] = __float2half_rn(vf);
}

__global__ void final_k(const __half* __restrict__ h3, const float* __restrict__ Wo,
                        const float* __restrict__ bo, float* __restrict__ out) {
    int b = blockIdx.x;
    int t = threadIdx.x;
    float s = 0.f;
#pragma unroll
    for (int c = t; c < 512; c += 128)
        s = fmaf(__half2float(h3[(size_t)b * 512 + c]), Wo[c], s);
#pragma unroll
    for (int o = 16; o > 0; o >>= 1) s += __shfl_down_sync(0xffffffffu, s, o);
    __shared__ float red[4];
    if ((t & 31) == 0) red[t >> 5] = s;
    __syncthreads();
    if (t == 0) out[b] = red[0] + red[1] + red[2] + red[3] + bo[0];
}

// ---------------- host launch ----------------
#define GADDR(p, sym) cudaGetSymbolAddress((void**)&p, sym)

extern "C" void kernel_launch(void* const* d_in, const int* in_sizes, int n_in,
                              void* d_out, int out_size) {
    const int*   drug    = (const int*)  d_in[0];
    const float* feature = (const float*)d_in[1];
    const float* emb     = (const float*)d_in[2];
    const float* dw1 = (const float*)d_in[3];  const float* db1 = (const float*)d_in[4];
    const float* dw2 = (const float*)d_in[5];  const float* db2 = (const float*)d_in[6];
    const float* dw3 = (const float*)d_in[7];  const float* db3 = (const float*)d_in[8];
    const float* fw1 = (const float*)d_in[9];  const float* fb1 = (const float*)d_in[10];
    const float* fw2 = (const float*)d_in[11]; const float* fb2 = (const float*)d_in[12];
    const float* fw3 = (const float*)d_in[13]; const float* fb3 = (const float*)d_in[14];
    const float* Wda = (const float*)d_in[15]; const float* bda = (const float*)d_in[16];
    const float* Wfa = (const float*)d_in[17]; const float* bfa = (const float*)d_in[18];
    const float* Watt= (const float*)d_in[19]; const float* batt= (const float*)d_in[20];
    const float* W1  = (const float*)d_in[21]; const float* b1  = (const float*)d_in[22];
    const float* W2  = (const float*)d_in[23]; const float* b2  = (const float*)d_in[24];
    const float* W3  = (const float*)d_in[25]; const float* b3  = (const float*)d_in[26];
    const float* Wo  = (const float*)d_in[27]; const float* bo  = (const float*)d_in[28];
    float* out = (float*)d_out;

    __half *x,*h1,*h2,*dc,*att,*hf1,*hf2,*fnn,*pair,*fh1,*fh2,*Am,*fatt,*fh3;
    __half *w1r,*w2r,*w3r,*fwm2,*fwm3,*WdaH,*WfaH,*WattH,*W1H,*W2H,*W3H;
    float *fwm1;
    GADDR(x, g_x); GADDR(h1, g_h1); GADDR(h2, g_h2);
    GADDR(dc, g_dc); GADDR(att, g_att);
    GADDR(hf1, g_hf1); GADDR(hf2, g_hf2); GADDR(fnn, g_fnn);
    GADDR(pair, g_pair); GADDR(fh1, g_fh1); GADDR(fh2, g_fh2);
    GADDR(Am, g_Am); GADDR(fatt, g_fatt); GADDR(fh3, g_fh3);
    GADDR(w1r, g_w1r); GADDR(w2r, g_w2r); GADDR(w3r, g_w3r);
    GADDR(fwm2, g_fwm2); GADDR(fwm3, g_fwm3);
    GADDR(WdaH, g_Wda); GADDR(WfaH, g_Wfa); GADDR(WattH, g_Watt);
    GADDR(W1H, g_W1); GADDR(W2H, g_W2); GADDR(W3H, g_W3);
    GADDR(fwm1, g_fwm1);

    cudaFuncSetAttribute(gemmW<0>, cudaFuncAttributeMaxDynamicSharedMemorySize, WSMEM);
    cudaFuncSetAttribute(gemmW<1>, cudaFuncAttributeMaxDynamicSharedMemorySize, WSMEM);
    cudaFuncSetAttribute(gemmW<3>, cudaFuncAttributeMaxDynamicSharedMemorySize, WSMEM);
    cudaFuncSetAttribute(gemmS<0>, cudaFuncAttributeMaxDynamicSharedMemorySize, SSMEM);
    cudaFuncSetAttribute(gemmS<1>, cudaFuncAttributeMaxDynamicSharedMemorySize, SSMEM);
    cudaFuncSetAttribute(gemmS<2>, cudaFuncAttributeMaxDynamicSharedMemorySize, SSMEM);

    // prep
    embed_h<<<(BATCH * LD * 32 + 255) / 256, 256>>>(drug, emb, x);
    reorder_w_h<<<(128 * 128 * 4 + 255) / 256, 256>>>(dw1, w1r, 128, 128, 4);
    reorder_w_h<<<(256 * 128 * 6 + 255) / 256, 256>>>(dw2, w2r, 256, 128, 6);
    reorder_w_h<<<(512 * 256 * 8 + 255) / 256, 256>>>(dw3, w3r, 512, 256, 8);
    midtap_f32<<<(128 * 7 + 255) / 256, 256>>>(fw1, fwm1, 128 * 7);

    // drug conv stack (wide-N tiles: half the A re-reads)
    gemmS<1><<<dim3(1, (BATCH * L1O) / 128), 256, SSMEM>>>(x, w1r, db1,
        nullptr, h1, 128, 512, L1O, (long)LD * 128, 128L, 1);
    gemmW<1><<<dim3(1, (BATCH * L2O) / 128), 256, WSMEM>>>(h1, w2r, db2,
        nullptr, h2, 256, 768, L2O, (long)L1O * 128, 128L, 1);
    gemmW<1><<<dim3(2, (BATCH * L3O) / 128), 256, WSMEM>>>(h2, w3r, db3,
        nullptr, dc, 512, 2048, L3O, (long)L2O * 256, 256L, 1);

    // feature branch
    midtap_h<<<(256 * 128 + 255) / 256, 256>>>(fw2, fwm2, 256 * 128);
    midtap_h<<<(512 * 256 + 255) / 256, 256>>>(fw3, fwm3, 512 * 256);
    conv_h<<<(512 * 512 + 255) / 256, 256>>>(Wda, WdaH, 512 * 512);
    conv_h<<<(512 * 512 + 255) / 256, 256>>>(Wfa, WfaH, 512 * 512);
    conv_h<<<(512 * 512 + 255) / 256, 256>>>(Watt, WattH, 512 * 512);

    feat1_k<<<(BATCH * 128) / 256, 256>>>(feature, fwm1, fb1, hf1);
    gemmS<1><<<dim3(2, BATCH / 128), 256, SSMEM>>>(hf1, fwm2, fb2,
        nullptr, hf2, 256, 128, BATCH, 0L, 128L, 1);
    gemmS<1><<<dim3(4, BATCH / 128), 256, SSMEM>>>(hf2, fwm3, fb3,
        nullptr, fnn, 512, 256, BATCH, 0L, 256L, 1);
    gemmS<0><<<dim3(4, BATCH / 128), 256, SSMEM>>>(fnn, WfaH, bfa,
        nullptr, fatt, 512, 512, BATCH, 0L, 512L, 1);

    // s = relu(dc @ Wda^T + bda + fatt[b]) fused
    gemmW<3><<<dim3(2, (BATCH * L3O) / 128), 256, WSMEM>>>(dc, WdaH, bda,
        fatt, att, 512, 512, BATCH * L3O, 0L, 512L, L3O);

    // A = s @ Watt^T + batt
    gemmW<0><<<dim3(2, (BATCH * L3O) / 128), 256, WSMEM>>>(att, WattH, batt,
        nullptr, Am, 512, 512, BATCH * L3O, 0L, 512L, 1);

    reduce_k<<<BATCH, 512>>>(dc, Am, fnn, pair);

    // FC head
    conv_h<<<(1024 * 1024 + 255) / 256, 256>>>(W1, W1H, 1024 * 1024);
    conv_h<<<(1024 * 1024 + 255) / 256, 256>>>(W2, W2H, 1024 * 1024);
    conv_h<<<(512 * 1024 + 255) / 256, 256>>>(W3, W3H, 512 * 1024);

    gemmS<2><<<dim3(8, BATCH / 128), 256, SSMEM>>>(pair, W1H, b1,
        nullptr, fh1, 1024, 1024, BATCH, 0L, 1024L, 1);
    gemmS<2><<<dim3(8, BATCH / 128), 256, SSMEM>>>(fh1, W2H, b2,
        nullptr, fh2, 1024, 1024, BATCH, 0L, 1024L, 1);
    gemmS<2><<<dim3(4, BATCH / 128), 256, SSMEM>>>(fh2, W3H, b3,
        nullptr, fh3, 512, 1024, BATCH, 0L, 1024L, 1);

    final_k<<<BATCH, 128>>>(fh3, Wo, bo, out);
}

// round 13
// speedup vs baseline: 1.1509x; 1.0136x over previous
#include <cuda_runtime.h>
#include <cuda_fp16.h>
#include <math.h>
#include <stdint.h>

// ---------------- problem constants ----------------
#define BATCH 2048
#define LD    100
#define DIM   128
#define L1O   97
#define L2O   92
#define L3O   85

// ---------------- scratch (device globals; allocation-free) ----------------
__device__ __half g_x  [BATCH * LD  * DIM];
__device__ __half g_h1 [BATCH * L1O * 128];
__device__ __half g_h2 [BATCH * L2O * 256];
__device__ __half g_dc [BATCH * L3O * 512];
__device__ __half g_att[BATCH * L3O * 512];
__device__ __half g_hf1[BATCH * 128];
__device__ __half g_hf2[BATCH * 256];
__device__ __half g_fnn[BATCH * 512];
__device__ __half g_pair[BATCH * 1024];
__device__ __half g_fh1[BATCH * 1024];
__device__ __half g_fh2[BATCH * 1024];
__device__ __half g_Am [BATCH * L3O * 512];
__device__ __half g_fatt[BATCH * 512];
__device__ __half g_fh3[BATCH * 512];
__device__ float  g_fwm1[128 * 7];
__device__ __half g_w1r[128 * 512];
__device__ __half g_w2r[256 * 768];
__device__ __half g_w3r[512 * 2048];
__device__ __half g_fwm2[256 * 128];
__device__ __half g_fwm3[512 * 256];
__device__ __half g_Wda[512 * 512];
__device__ __half g_Wfa[512 * 512];
__device__ __half g_Watt[512 * 512];
__device__ __half g_W1[1024 * 1024];
__device__ __half g_W2[1024 * 1024];
__device__ __half g_W3[512 * 1024];

// ---------------- helpers ----------------
__device__ __forceinline__ uint32_t smem_u32(const void* p) {
    uint32_t a;
    asm("{ .reg .u64 t; cvta.to.shared.u64 t, %1; cvt.u32.u64 %0, t; }"
        : "=r"(a) : "l"(p));
    return a;
}
__device__ __forceinline__ void ldm4(uint32_t* r, uint32_t saddr) {
    asm volatile("ldmatrix.sync.aligned.m8n8.x4.shared.b16 {%0,%1,%2,%3}, [%4];"
        : "=r"(r[0]), "=r"(r[1]), "=r"(r[2]), "=r"(r[3]) : "r"(saddr));
}
__device__ __forceinline__ void mma16816(float* d, const uint32_t* a,
                                         uint32_t b0, uint32_t b1) {
    asm volatile(
        "mma.sync.aligned.m16n8k16.row.col.f32.f16.f16.f32 "
        "{%0,%1,%2,%3}, {%4,%5,%6,%7}, {%8,%9}, {%0,%1,%2,%3};"
        : "+f"(d[0]), "+f"(d[1]), "+f"(d[2]), "+f"(d[3])
        : "r"(a[0]), "r"(a[1]), "r"(a[2]), "r"(a[3]), "r"(b0), "r"(b1));
}
#define CPA16(dst, src) \
    asm volatile("cp.async.cg.shared.global [%0], [%1], 16;" :: "r"(dst), "l"(src) : "memory")
#define CPCOMMIT() asm volatile("cp.async.commit_group;" ::: "memory")
template <int NW> __device__ __forceinline__ void cpwait() {
    asm volatile("cp.async.wait_group %0;" :: "n"(NW) : "memory");
}

template <int ACT>
__device__ __forceinline__ void epi_store(float vx, float vy, long rowb, int n,
                                          __half* C) {
    if (ACT == 1 || ACT == 3) {
        vx = fmaxf(vx, 0.f); vy = fmaxf(vy, 0.f);
    } else if (ACT == 2) {
        vx = vx > 0.f ? vx : 0.01f * vx;
        vy = vy > 0.f ? vy : 0.01f * vy;
    }
    *(__half2*)(C + rowb + n) = __floats2half2_rn(vx, vy);
}

#define ROWB   80u

// ---------------- wide GEMM: CTA 128(M)x256(N), 8 warps (2m x 4n), warp 64x64 ----------------
#define WAPLN  10240u
#define WSTG   30720u
#define WSMEM  (3 * 30720)

template <int ACT>
__global__ __launch_bounds__(256, 1)
void gemmW(const __half* __restrict__ A, const __half* __restrict__ W,
           const float* __restrict__ bias, const __half* __restrict__ extra,
           __half* __restrict__ C,
           int N, int K, int Lout, long sOuter, long sInner, int rowdiv) {
    extern __shared__ char sm[];
    const uint32_t smb = smem_u32(sm);
    const int tid = threadIdx.x;
    const int wid = tid >> 5, lane = tid & 31;
    const int m0 = blockIdx.y * 128, n0 = blockIdx.x * 256;
    const int wm = wid >> 2, wn = wid & 3;

    const int lrow = tid >> 1;
    const int lseg = tid & 1;
    const int mrow = m0 + lrow;
    const __half* aP = A + (long)(mrow / Lout) * sOuter + (long)(mrow % Lout) * sInner
                         + lseg * 16;
    const uint32_t aDst = smb + (uint32_t)lrow * ROWB + (uint32_t)lseg * 32u;
    const __half* bP = W + (long)(n0 + tid) * K;
    const uint32_t bDst = smb + WAPLN + (uint32_t)tid * ROWB;

    const int laneR = lane & 15;
    const uint32_t laneC = (uint32_t)(lane >> 4) * 16u;
    const uint32_t aBase = smb + (uint32_t)(wm * 64 + laneR) * ROWB + laneC;
    const uint32_t bBase = smb + WAPLN + (uint32_t)(wn * 64 + laneR) * ROWB + laneC;

    float acc[4][8][4];
#pragma unroll
    for (int i = 0; i < 4; i++)
#pragma unroll
        for (int j = 0; j < 8; j++)
#pragma unroll
            for (int k = 0; k < 4; k++) acc[i][j][k] = 0.f;

    const int T = K / 32;
    {
#pragma unroll
        for (int s = 0; s < 2; s++) CPA16(aDst + s * 16u, aP + s * 8);
#pragma unroll
        for (int s = 0; s < 4; s++) CPA16(bDst + s * 16u, bP + s * 8);
        CPCOMMIT();
    }
    if (T > 1) {
#pragma unroll
        for (int s = 0; s < 2; s++) CPA16(aDst + WSTG + s * 16u, aP + 32 + s * 8);
#pragma unroll
        for (int s = 0; s < 4; s++) CPA16(bDst + WSTG + s * 16u, bP + 32 + s * 8);
        CPCOMMIT();
    }

    int buf = 0;
    int buf2 = (T > 2) ? 2 : 0;
    for (int t = 0; t < T; ++t) {
        if (t + 2 < T) {
            const int k0 = (t + 2) * 32;
            const uint32_t sb = (uint32_t)buf2 * WSTG;
#pragma unroll
            for (int s = 0; s < 2; s++) CPA16(aDst + sb + s * 16u, aP + k0 + s * 8);
#pragma unroll
            for (int s = 0; s < 4; s++) CPA16(bDst + sb + s * 16u, bP + k0 + s * 8);
            CPCOMMIT();
            cpwait<2>();
            if (++buf2 == 3) buf2 = 0;
        } else if (t + 1 < T) {
            cpwait<1>();
        } else {
            cpwait<0>();
        }
        __syncthreads();

        const uint32_t soff = (uint32_t)buf * WSTG;
#pragma unroll
        for (int j = 0; j < 2; j++) {
            const uint32_t ja = soff + (uint32_t)j * 32u;
            uint32_t af[4][4], bf[4][4];
#pragma unroll
            for (int mt = 0; mt < 4; mt++)
                ldm4(af[mt], aBase + ja + (uint32_t)mt * (16u * ROWB));
#pragma unroll
            for (int nt = 0; nt < 4; nt++)
                ldm4(bf[nt], bBase + ja + (uint32_t)nt * (16u * ROWB));
#pragma unroll
            for (int nt = 0; nt < 4; nt++)
#pragma unroll
                for (int mt = 0; mt < 4; mt++) {
                    mma16816(acc[mt][2 * nt],     af[mt], bf[nt][0], bf[nt][2]);
                    mma16816(acc[mt][2 * nt + 1], af[mt], bf[nt][1], bf[nt][3]);
                }
        }
        __syncthreads();
        if (++buf == 3) buf = 0;
    }

    const int lr2 = lane >> 2;
    const int lc2 = (lane & 3) * 2;
#pragma unroll
    for (int mt = 0; mt < 4; mt++) {
#pragma unroll
        for (int h = 0; h < 2; h++) {
            const long m = (long)m0 + wm * 64 + mt * 16 + h * 8 + lr2;
            const long rowb = m * (long)N;
            const __half* erow = (ACT == 3) ? (extra + (long)(m / rowdiv) * N) : nullptr;
#pragma unroll
            for (int nt2 = 0; nt2 < 8; nt2++) {
                const int n = n0 + wn * 64 + nt2 * 8 + lc2;
                float vx = acc[mt][nt2][2 * h]     + bias[n];
                float vy = acc[mt][nt2][2 * h + 1] + bias[n + 1];
                if (ACT == 3) {
                    float2 e = __half22float2(*(const __half2*)(erow + n));
                    vx += e.x; vy += e.y;
                }
                epi_store<ACT>(vx, vy, rowb, n, C);
            }
        }
    }
}

// ---------------- small GEMM: CTA 128x128, 8 warps, warp 32x64, 3 stages ----------------
#define SPLN   10240u
#define SSTG   20480u
#define SSMEM  (3 * 20480)

template <int ACT>
__global__ __launch_bounds__(256, 1)
void gemmS(const __half* __restrict__ A, const __half* __restrict__ W,
           const float* __restrict__ bias, const __half* __restrict__ extra,
           __half* __restrict__ C,
           int N, int K, int Lout, long sOuter, long sInner, int rowdiv) {
    extern __shared__ char sm[];
    const uint32_t smb = smem_u32(sm);
    const int tid = threadIdx.x;
    const int wid = tid >> 5, lane = tid & 31;
    const int m0 = blockIdx.y * 128, n0 = blockIdx.x * 128;
    const int wm = wid >> 1, wn = wid & 1;

    const int lrow = tid >> 1;
    const int lc   = (tid & 1) * 16;
    const int mrow = m0 + lrow;
    const __half* aP = A + (long)(mrow / Lout) * sOuter + (long)(mrow % Lout) * sInner + lc;
    const __half* bP = W + (long)(n0 + lrow) * K + lc;
    const uint32_t rowDst = smb + (uint32_t)lrow * ROWB + (uint32_t)(tid & 1) * 32u;

    const int laneR = lane & 15;
    const uint32_t laneC = (uint32_t)(lane >> 4) * 16u;
    const uint32_t aBase = smb + (uint32_t)(wm * 32 + laneR) * ROWB + laneC;
    const uint32_t bBase = smb + SPLN + (uint32_t)(wn * 64 + laneR) * ROWB + laneC;

    float acc[2][8][4];
#pragma unroll
    for (int i = 0; i < 2; i++)
#pragma unroll
        for (int j = 0; j < 8; j++)
#pragma unroll
            for (int k = 0; k < 4; k++) acc[i][j][k] = 0.f;

    const int T = K / 32;
    {
#pragma unroll
        for (int s = 0; s < 2; s++) {
            CPA16(rowDst + s * 16u,        aP + s * 8);
            CPA16(rowDst + SPLN + s * 16u, bP + s * 8);
        }
        CPCOMMIT();
    }
    if (T > 1) {
#pragma unroll
        for (int s = 0; s < 2; s++) {
            CPA16(rowDst + SSTG + s * 16u,        aP + 32 + s * 8);
            CPA16(rowDst + SSTG + SPLN + s * 16u, bP + 32 + s * 8);
        }
        CPCOMMIT();
    }

    int buf = 0;
    int buf2 = (T > 2) ? 2 : 0;
    for (int t = 0; t < T; ++t) {
        if (t + 2 < T) {
            const int k0 = (t + 2) * 32;
            const uint32_t sb = (uint32_t)buf2 * SSTG;
#pragma unroll
            for (int s = 0; s < 2; s++) {
                CPA16(rowDst + sb + s * 16u,        aP + k0 + s * 8);
                CPA16(rowDst + sb + SPLN + s * 16u, bP + k0 + s * 8);
            }
            CPCOMMIT();
            cpwait<2>();
            if (++buf2 == 3) buf2 = 0;
        } else if (t + 1 < T) {
            cpwait<1>();
        } else {
            cpwait<0>();
        }
        __syncthreads();

        const uint32_t soff = (uint32_t)buf * SSTG;
#pragma unroll
        for (int j = 0; j < 2; j++) {
            const uint32_t ja = soff + (uint32_t)j * 32u;
            uint32_t af[2][4], bf[4][4];
#pragma unroll
            for (int mt = 0; mt < 2; mt++)
                ldm4(af[mt], aBase + ja + (uint32_t)mt * (16u * ROWB));
#pragma unroll
            for (int nt = 0; nt < 4; nt++)
                ldm4(bf[nt], bBase + ja + (uint32_t)nt * (16u * ROWB));
#pragma unroll
            for (int nt = 0; nt < 4; nt++)
#pragma unroll
                for (int mt = 0; mt < 2; mt++) {
                    mma16816(acc[mt][2 * nt],     af[mt], bf[nt][0], bf[nt][2]);
                    mma16816(acc[mt][2 * nt + 1], af[mt], bf[nt][1], bf[nt][3]);
                }
        }
        __syncthreads();
        if (++buf == 3) buf = 0;
    }

    const int lr2 = lane >> 2;
    const int lc2 = (lane & 3) * 2;
#pragma unroll
    for (int mt = 0; mt < 2; mt++) {
#pragma unroll
        for (int h = 0; h < 2; h++) {
            const long m = (long)m0 + wm * 32 + mt * 16 + h * 8 + lr2;
            const long rowb = m * (long)N;
            const __half* erow = (ACT == 3) ? (extra + (long)(m / rowdiv) * N) : nullptr;
#pragma unroll
            for (int nt2 = 0; nt2 < 8; nt2++) {
                const int n = n0 + wn * 64 + nt2 * 8 + lc2;
                float vx = acc[mt][nt2][2 * h]     + bias[n];
                float vy = acc[mt][nt2][2 * h + 1] + bias[n + 1];
                if (ACT == 3) {
                    float2 e = __half22float2(*(const __half2*)(erow + n));
                    vx += e.x; vy += e.y;
                }
                epi_store<ACT>(vx, vy, rowb, n, C);
            }
        }
    }
}

// ---------------- prep / glue kernels ----------------
__global__ void embed_h(const int* __restrict__ drug, const float* __restrict__ emb,
                        __half* __restrict__ x) {
    int idx = blockIdx.x * blockDim.x + threadIdx.x;
    const int total = BATCH * LD * (DIM / 4);
    if (idx >= total) return;
    int d4 = idx & 31;
    int bl = idx >> 5;
    int tok = drug[bl];
    float4 v = ((const float4*)emb)[(size_t)tok * 32 + d4];
    size_t pos = (size_t)bl * 128 + d4 * 4;
    *(__half2*)(x + pos)     = __floats2half2_rn(v.x, v.y);
    *(__half2*)(x + pos + 2) = __floats2half2_rn(v.z, v.w);
}

__global__ void reorder_w_h(const float* __restrict__ w, __half* __restrict__ wr,
                            int O, int Ci, int Kw) {
    int idx = blockIdx.x * blockDim.x + threadIdx.x;
    int total = O * Ci * Kw;
    if (idx >= total) return;
    int o = idx / (Ci * Kw);
    int rr = idx - o * (Ci * Kw);
    int i = rr / Kw;
    int k = rr - i * Kw;
    wr[(size_t)o * Ci * Kw + k * Ci + i] = __float2half_rn(w[idx]);
}

__global__ void midtap_h(const float* __restrict__ w, __half* __restrict__ wr, int total) {
    int idx = blockIdx.x * blockDim.x + threadIdx.x;
    if (idx >= total) return;
    wr[idx] = __float2half_rn(w[idx * 3 + 1]);
}

__global__ void midtap_f32(const float* __restrict__ w, float* __restrict__ wr, int total) {
    int idx = blockIdx.x * blockDim.x + threadIdx.x;
    if (idx >= total) return;
    wr[idx] = w[idx * 3 + 1];
}

__global__ void conv_h(const float* __restrict__ w, __half* __restrict__ wr, int total) {
    int idx = blockIdx.x * blockDim.x + threadIdx.x;
    if (idx >= total) return;
    wr[idx] = __float2half_rn(w[idx]);
}

__global__ void feat1_k(const float* __restrict__ feat, const float* __restrict__ wm,
                        const float* __restrict__ bias, __half* __restrict__ o1) {
    int idx = blockIdx.x * blockDim.x + threadIdx.x;
    if (idx >= BATCH * 128) return;
    int b = idx >> 7, o = idx & 127;
    float s = bias[o];
#pragma unroll
    for (int i = 0; i < 7; i++) s = fmaf(feat[b * 7 + i], wm[o * 7 + i], s);
    o1[idx] = __float2half_rn(fmaxf(s, 0.f));
}

__global__ void reduce_k(const __half* __restrict__ dc, const __half* __restrict__ Am,
                         const __half* __restrict__ fnn,
                         __half* __restrict__ pair) {
    int b = blockIdx.x;
    int c = threadIdx.x;
    const size_t base = (size_t)b * L3O * 512 + c;
    float mx = -1e30f, smv = 0.f;
#pragma unroll 5
    for (int l = 0; l < L3O; l++) {
        float a = __half2float(Am[base + (size_t)l * 512]);
        float d = __half2float(dc[base + (size_t)l * 512]);
        float sg = 1.f / (1.f + expf(-a));
        mx = fmaxf(mx, d * (0.5f + sg));
        smv += a;
    }
    float fsig = 1.f / (1.f + expf(-smv * (1.0f / L3O)));
    float vf = __half2float(fnn[(size_t)b * 512 + c]) * (0.5f + fsig);
    pair[(size_t)b * 1024 + c]       = __float2half_rn(mx);
    pair[(size_t)b * 1024 + 512 + c] = __float2half_rn(vf);
}

__global__ void final_k(const __half* __restrict__ h3, const float* __restrict__ Wo,
                        const float* __restrict__ bo, float* __restrict__ out) {
    int b = blockIdx.x;
    int t = threadIdx.x;
    float s = 0.f;
#pragma unroll
    for (int c = t; c < 512; c += 128)
        s = fmaf(__half2float(h3[(size_t)b * 512 + c]), Wo[c], s);
#pragma unroll
    for (int o = 16; o > 0; o >>= 1) s += __shfl_down_sync(0xffffffffu, s, o);
    __shared__ float red[4];
    if ((t & 31) == 0) red[t >> 5] = s;
    __syncthreads();
    if (t == 0) out[b] = red[0] + red[1] + red[2] + red[3] + bo[0];
}

// ---------------- host launch ----------------
#define GADDR(p, sym) cudaGetSymbolAddress((void**)&p, sym)

extern "C" void kernel_launch(void* const* d_in, const int* in_sizes, int n_in,
                              void* d_out, int out_size) {
    const int*   drug    = (const int*)  d_in[0];
    const float* feature = (const float*)d_in[1];
    const float* emb     = (const float*)d_in[2];
    const float* dw1 = (const float*)d_in[3];  const float* db1 = (const float*)d_in[4];
    const float* dw2 = (const float*)d_in[5];  const float* db2 = (const float*)d_in[6];
    const float* dw3 = (const float*)d_in[7];  const float* db3 = (const float*)d_in[8];
    const float* fw1 = (const float*)d_in[9];  const float* fb1 = (const float*)d_in[10];
    const float* fw2 = (const float*)d_in[11]; const float* fb2 = (const float*)d_in[12];
    const float* fw3 = (const float*)d_in[13]; const float* fb3 = (const float*)d_in[14];
    const float* Wda = (const float*)d_in[15]; const float* bda = (const float*)d_in[16];
    const float* Wfa = (const float*)d_in[17]; const float* bfa = (const float*)d_in[18];
    const float* Watt= (const float*)d_in[19]; const float* batt= (const float*)d_in[20];
    const float* W1  = (const float*)d_in[21]; const float* b1  = (const float*)d_in[22];
    const float* W2  = (const float*)d_in[23]; const float* b2  = (const float*)d_in[24];
    const float* W3  = (const float*)d_in[25]; const float* b3  = (const float*)d_in[26];
    const float* Wo  = (const float*)d_in[27]; const float* bo  = (const float*)d_in[28];
    float* out = (float*)d_out;

    __half *x,*h1,*h2,*dc,*att,*hf1,*hf2,*fnn,*pair,*fh1,*fh2,*Am,*fatt,*fh3;
    __half *w1r,*w2r,*w3r,*fwm2,*fwm3,*WdaH,*WfaH,*WattH,*W1H,*W2H,*W3H;
    float *fwm1;
    GADDR(x, g_x); GADDR(h1, g_h1); GADDR(h2, g_h2);
    GADDR(dc, g_dc); GADDR(att, g_att);
    GADDR(hf1, g_hf1); GADDR(hf2, g_hf2); GADDR(fnn, g_fnn);
    GADDR(pair, g_pair); GADDR(fh1, g_fh1); GADDR(fh2, g_fh2);
    GADDR(Am, g_Am); GADDR(fatt, g_fatt); GADDR(fh3, g_fh3);
    GADDR(w1r, g_w1r); GADDR(w2r, g_w2r); GADDR(w3r, g_w3r);
    GADDR(fwm2, g_fwm2); GADDR(fwm3, g_fwm3);
    GADDR(WdaH, g_Wda); GADDR(WfaH, g_Wfa); GADDR(WattH, g_Watt);
    GADDR(W1H, g_W1); GADDR(W2H, g_W2); GADDR(W3H, g_W3);
    GADDR(fwm1, g_fwm1);

    cudaFuncSetAttribute(gemmW<0>, cudaFuncAttributeMaxDynamicSharedMemorySize, WSMEM);
    cudaFuncSetAttribute(gemmW<1>, cudaFuncAttributeMaxDynamicSharedMemorySize, WSMEM);
    cudaFuncSetAttribute(gemmW<3>, cudaFuncAttributeMaxDynamicSharedMemorySize, WSMEM);
    cudaFuncSetAttribute(gemmS<0>, cudaFuncAttributeMaxDynamicSharedMemorySize, SSMEM);
    cudaFuncSetAttribute(gemmS<1>, cudaFuncAttributeMaxDynamicSharedMemorySize, SSMEM);
    cudaFuncSetAttribute(gemmS<2>, cudaFuncAttributeMaxDynamicSharedMemorySize, SSMEM);

    // side stream + fork/join events; created once on the first (uncaptured)
    // correctness call, reused verbatim on the capture call -> identical work.
    static cudaStream_t s2 = nullptr;
    static cudaEvent_t evFork = nullptr, evJoin = nullptr;
    if (s2 == nullptr) {
        cudaStreamCreateWithFlags(&s2, cudaStreamNonBlocking);
        cudaEventCreateWithFlags(&evFork, cudaEventDisableTiming);
        cudaEventCreateWithFlags(&evJoin, cudaEventDisableTiming);
    }

    // ---- fork ----
    cudaEventRecord(evFork, 0);
    cudaStreamWaitEvent(s2, evFork, 0);

    // ---- stream 0: drug conv chain ----
    embed_h<<<(BATCH * LD * 32 + 255) / 256, 256>>>(drug, emb, x);
    reorder_w_h<<<(128 * 128 * 4 + 255) / 256, 256>>>(dw1, w1r, 128, 128, 4);
    reorder_w_h<<<(256 * 128 * 6 + 255) / 256, 256>>>(dw2, w2r, 256, 128, 6);
    reorder_w_h<<<(512 * 256 * 8 + 255) / 256, 256>>>(dw3, w3r, 512, 256, 8);

    gemmS<1><<<dim3(1, (BATCH * L1O) / 128), 256, SSMEM>>>(x, w1r, db1,
        nullptr, h1, 128, 512, L1O, (long)LD * 128, 128L, 1);
    gemmW<1><<<dim3(1, (BATCH * L2O) / 128), 256, WSMEM>>>(h1, w2r, db2,
        nullptr, h2, 256, 768, L2O, (long)L1O * 128, 128L, 1);
    gemmW<1><<<dim3(2, (BATCH * L3O) / 128), 256, WSMEM>>>(h2, w3r, db3,
        nullptr, dc, 512, 2048, L3O, (long)L2O * 256, 256L, 1);

    // ---- stream s2: feature branch + all remaining weight conversions ----
    midtap_f32<<<(128 * 7 + 255) / 256, 256, 0, s2>>>(fw1, fwm1, 128 * 7);
    midtap_h<<<(256 * 128 + 255) / 256, 256, 0, s2>>>(fw2, fwm2, 256 * 128);
    midtap_h<<<(512 * 256 + 255) / 256, 256, 0, s2>>>(fw3, fwm3, 512 * 256);
    conv_h<<<(512 * 512 + 255) / 256, 256, 0, s2>>>(Wda, WdaH, 512 * 512);
    conv_h<<<(512 * 512 + 255) / 256, 256, 0, s2>>>(Wfa, WfaH, 512 * 512);
    conv_h<<<(512 * 512 + 255) / 256, 256, 0, s2>>>(Watt, WattH, 512 * 512);
    conv_h<<<(1024 * 1024 + 255) / 256, 256, 0, s2>>>(W1, W1H, 1024 * 1024);
    conv_h<<<(1024 * 1024 + 255) / 256, 256, 0, s2>>>(W2, W2H, 1024 * 1024);
    conv_h<<<(512 * 1024 + 255) / 256, 256, 0, s2>>>(W3, W3H, 512 * 1024);

    feat1_k<<<(BATCH * 128) / 256, 256, 0, s2>>>(feature, fwm1, fb1, hf1);
    gemmS<1><<<dim3(2, BATCH / 128), 256, SSMEM, s2>>>(hf1, fwm2, fb2,
        nullptr, hf2, 256, 128, BATCH, 0L, 128L, 1);
    gemmS<1><<<dim3(4, BATCH / 128), 256, SSMEM, s2>>>(hf2, fwm3, fb3,
        nullptr, fnn, 512, 256, BATCH, 0L, 256L, 1);
    gemmS<0><<<dim3(4, BATCH / 128), 256, SSMEM, s2>>>(fnn, WfaH, bfa,
        nullptr, fatt, 512, 512, BATCH, 0L, 512L, 1);

    cudaEventRecord(evJoin, s2);

    // ---- join: att chain needs fatt/WdaH/WattH; FC needs W1H..W3H ----
    cudaStreamWaitEvent(0, evJoin, 0);

    gemmW<3><<<dim3(2, (BATCH * L3O) / 128), 256, WSMEM>>>(dc, WdaH, bda,
        fatt, att, 512, 512, BATCH * L3O, 0L, 512L, L3O);
    gemmW<0><<<dim3(2, (BATCH * L3O) / 128), 256, WSMEM>>>(att, WattH, batt,
        nullptr, Am, 512, 512, BATCH * L3O, 0L, 512L, 1);

    reduce_k<<<BATCH, 512>>>(dc, Am, fnn, pair);

    gemmS<2><<<dim3(8, BATCH / 128), 256, SSMEM>>>(pair, W1H, b1,
        nullptr, fh1, 1024, 1024, BATCH, 0L, 1024L, 1);
    gemmS<2><<<dim3(8, BATCH / 128), 256, SSMEM>>>(fh1, W2H, b2,
        nullptr, fh2, 1024, 1024, BATCH, 0L, 1024L, 1);
    gemmS<2><<<dim3(4, BATCH / 128), 256, SSMEM>>>(fh2, W3H, b3,
        nullptr, fh3, 512, 1024, BATCH, 0L, 1024L, 1);

    final_k<<<BATCH, 128>>>(fh3, Wo, bo, out);
}

// round 14
// speedup vs baseline: 1.1513x; 1.0004x over previous
#include <cuda_runtime.h>
#include <cuda_fp16.h>
#include <math.h>
#include <stdint.h>

// ---------------- problem constants ----------------
#define BATCH 2048
#define LD    100
#define DIM   128
#define L1O   97
#define L2O   92
#define L3O   85

// ---------------- scratch (device globals; allocation-free) ----------------
__device__ __half g_x  [BATCH * LD  * DIM];
__device__ __half g_h1 [BATCH * L1O * 128];
__device__ __half g_h2 [BATCH * L2O * 256];
__device__ __half g_dc [BATCH * L3O * 512];
__device__ __half g_att[BATCH * L3O * 512];
__device__ __half g_hf1[BATCH * 128];
__device__ __half g_hf2[BATCH * 256];
__device__ __half g_fnn[BATCH * 512];
__device__ __half g_pair[BATCH * 1024];
__device__ __half g_fh1[BATCH * 1024];
__device__ __half g_fh2[BATCH * 1024];
__device__ __half g_Am [BATCH * L3O * 512];
__device__ __half g_fatt[BATCH * 512];
__device__ __half g_fh3[BATCH * 512];
__device__ float  g_fwm1[128 * 7];
__device__ __half g_w1r[128 * 512];
__device__ __half g_w2r[256 * 768];
__device__ __half g_w3r[512 * 2048];
__device__ __half g_fwm2[256 * 128];
__device__ __half g_fwm3[512 * 256];
__device__ __half g_Wda[512 * 512];
__device__ __half g_Wfa[512 * 512];
__device__ __half g_Watt[512 * 512];
__device__ __half g_W1[1024 * 1024];
__device__ __half g_W2[1024 * 1024];
__device__ __half g_W3[512 * 1024];

// ---------------- helpers ----------------
__device__ __forceinline__ uint32_t smem_u32(const void* p) {
    uint32_t a;
    asm("{ .reg .u64 t; cvta.to.shared.u64 t, %1; cvt.u32.u64 %0, t; }"
        : "=r"(a) : "l"(p));
    return a;
}
__device__ __forceinline__ void ldm4(uint32_t* r, uint32_t saddr) {
    asm volatile("ldmatrix.sync.aligned.m8n8.x4.shared.b16 {%0,%1,%2,%3}, [%4];"
        : "=r"(r[0]), "=r"(r[1]), "=r"(r[2]), "=r"(r[3]) : "r"(saddr));
}
__device__ __forceinline__ void mma16816(float* d, const uint32_t* a,
                                         uint32_t b0, uint32_t b1) {
    asm volatile(
        "mma.sync.aligned.m16n8k16.row.col.f32.f16.f16.f32 "
        "{%0,%1,%2,%3}, {%4,%5,%6,%7}, {%8,%9}, {%0,%1,%2,%3};"
        : "+f"(d[0]), "+f"(d[1]), "+f"(d[2]), "+f"(d[3])
        : "r"(a[0]), "r"(a[1]), "r"(a[2]), "r"(a[3]), "r"(b0), "r"(b1));
}
#define CPA16(dst, src) \
    asm volatile("cp.async.cg.shared.global [%0], [%1], 16;" :: "r"(dst), "l"(src) : "memory")
#define CPCOMMIT() asm volatile("cp.async.commit_group;" ::: "memory")
template <int NW> __device__ __forceinline__ void cpwait() {
    asm volatile("cp.async.wait_group %0;" :: "n"(NW) : "memory");
}

template <int ACT>
__device__ __forceinline__ void epi_store(float vx, float vy, long rowb, int n,
                                          __half* C) {
    if (ACT == 1 || ACT == 3) {
        vx = fmaxf(vx, 0.f); vy = fmaxf(vy, 0.f);
    } else if (ACT == 2) {
        vx = vx > 0.f ? vx : 0.01f * vx;
        vy = vy > 0.f ? vy : 0.01f * vy;
    }
    *(__half2*)(C + rowb + n) = __floats2half2_rn(vx, vy);
}

#define ROWB   80u

// ---------------- wide GEMM: CTA 128(M)x256(N), 8 warps (2m x 4n), warp 64x64 ----------------
#define WAPLN  10240u
#define WSTG   30720u
#define WSMEM  (3 * 30720)

template <int ACT>
__global__ __launch_bounds__(256, 1)
void gemmW(const __half* __restrict__ A, const __half* __restrict__ W,
           const float* __restrict__ bias, const __half* __restrict__ extra,
           __half* __restrict__ C,
           int N, int K, int Lout, long sOuter, long sInner, int rowdiv) {
    extern __shared__ char sm[];
    const uint32_t smb = smem_u32(sm);
    const int tid = threadIdx.x;
    const int wid = tid >> 5, lane = tid & 31;
    const int m0 = blockIdx.y * 128, n0 = blockIdx.x * 256;
    const int wm = wid >> 2, wn = wid & 3;

    const int lrow = tid >> 1;
    const int lseg = tid & 1;
    const int mrow = m0 + lrow;
    const __half* aP = A + (long)(mrow / Lout) * sOuter + (long)(mrow % Lout) * sInner
                         + lseg * 16;
    const uint32_t aDst = smb + (uint32_t)lrow * ROWB + (uint32_t)lseg * 32u;
    const __half* bP = W + (long)(n0 + tid) * K;
    const uint32_t bDst = smb + WAPLN + (uint32_t)tid * ROWB;

    const int laneR = lane & 15;
    const uint32_t laneC = (uint32_t)(lane >> 4) * 16u;
    const uint32_t aBase = smb + (uint32_t)(wm * 64 + laneR) * ROWB + laneC;
    const uint32_t bBase = smb + WAPLN + (uint32_t)(wn * 64 + laneR) * ROWB + laneC;

    float acc[4][8][4];
#pragma unroll
    for (int i = 0; i < 4; i++)
#pragma unroll
        for (int j = 0; j < 8; j++)
#pragma unroll
            for (int k = 0; k < 4; k++) acc[i][j][k] = 0.f;

    const int T = K / 32;
    {
#pragma unroll
        for (int s = 0; s < 2; s++) CPA16(aDst + s * 16u, aP + s * 8);
#pragma unroll
        for (int s = 0; s < 4; s++) CPA16(bDst + s * 16u, bP + s * 8);
        CPCOMMIT();
    }
    if (T > 1) {
#pragma unroll
        for (int s = 0; s < 2; s++) CPA16(aDst + WSTG + s * 16u, aP + 32 + s * 8);
#pragma unroll
        for (int s = 0; s < 4; s++) CPA16(bDst + WSTG + s * 16u, bP + 32 + s * 8);
        CPCOMMIT();
    }

    int buf = 0;
    int buf2 = (T > 2) ? 2 : 0;
    for (int t = 0; t < T; ++t) {
        if (t + 2 < T) {
            const int k0 = (t + 2) * 32;
            const uint32_t sb = (uint32_t)buf2 * WSTG;
#pragma unroll
            for (int s = 0; s < 2; s++) CPA16(aDst + sb + s * 16u, aP + k0 + s * 8);
#pragma unroll
            for (int s = 0; s < 4; s++) CPA16(bDst + sb + s * 16u, bP + k0 + s * 8);
            CPCOMMIT();
            cpwait<2>();
            if (++buf2 == 3) buf2 = 0;
        } else if (t + 1 < T) {
            cpwait<1>();
        } else {
            cpwait<0>();
        }
        __syncthreads();

        const uint32_t soff = (uint32_t)buf * WSTG;
#pragma unroll
        for (int j = 0; j < 2; j++) {
            const uint32_t ja = soff + (uint32_t)j * 32u;
            uint32_t af[4][4], bf[4][4];
#pragma unroll
            for (int mt = 0; mt < 4; mt++)
                ldm4(af[mt], aBase + ja + (uint32_t)mt * (16u * ROWB));
#pragma unroll
            for (int nt = 0; nt < 4; nt++)
                ldm4(bf[nt], bBase + ja + (uint32_t)nt * (16u * ROWB));
#pragma unroll
            for (int nt = 0; nt < 4; nt++)
#pragma unroll
                for (int mt = 0; mt < 4; mt++) {
                    mma16816(acc[mt][2 * nt],     af[mt], bf[nt][0], bf[nt][2]);
                    mma16816(acc[mt][2 * nt + 1], af[mt], bf[nt][1], bf[nt][3]);
                }
        }
        __syncthreads();
        if (++buf == 3) buf = 0;
    }

    const int lr2 = lane >> 2;
    const int lc2 = (lane & 3) * 2;
#pragma unroll
    for (int mt = 0; mt < 4; mt++) {
#pragma unroll
        for (int h = 0; h < 2; h++) {
            const long m = (long)m0 + wm * 64 + mt * 16 + h * 8 + lr2;
            const long rowb = m * (long)N;
            const __half* erow = (ACT == 3) ? (extra + (long)(m / rowdiv) * N) : nullptr;
#pragma unroll
            for (int nt2 = 0; nt2 < 8; nt2++) {
                const int n = n0 + wn * 64 + nt2 * 8 + lc2;
                float vx = acc[mt][nt2][2 * h]     + bias[n];
                float vy = acc[mt][nt2][2 * h + 1] + bias[n + 1];
                if (ACT == 3) {
                    float2 e = __half22float2(*(const __half2*)(erow + n));
                    vx += e.x; vy += e.y;
                }
                epi_store<ACT>(vx, vy, rowb, n, C);
            }
        }
    }
}

// ---------------- small GEMM: CTA 128x128, 8 warps, warp 32x64, 3 stages ----------------
#define SPLN   10240u
#define SSTG   20480u
#define SSMEM  (3 * 20480)

template <int ACT>
__global__ __launch_bounds__(256, 1)
void gemmS(const __half* __restrict__ A, const __half* __restrict__ W,
           const float* __restrict__ bias, const __half* __restrict__ extra,
           __half* __restrict__ C,
           int N, int K, int Lout, long sOuter, long sInner, int rowdiv) {
    extern __shared__ char sm[];
    const uint32_t smb = smem_u32(sm);
    const int tid = threadIdx.x;
    const int wid = tid >> 5, lane = tid & 31;
    const int m0 = blockIdx.y * 128, n0 = blockIdx.x * 128;
    const int wm = wid >> 1, wn = wid & 1;

    const int lrow = tid >> 1;
    const int lc   = (tid & 1) * 16;
    const int mrow = m0 + lrow;
    const __half* aP = A + (long)(mrow / Lout) * sOuter + (long)(mrow % Lout) * sInner + lc;
    const __half* bP = W + (long)(n0 + lrow) * K + lc;
    const uint32_t rowDst = smb + (uint32_t)lrow * ROWB + (uint32_t)(tid & 1) * 32u;

    const int laneR = lane & 15;
    const uint32_t laneC = (uint32_t)(lane >> 4) * 16u;
    const uint32_t aBase = smb + (uint32_t)(wm * 32 + laneR) * ROWB + laneC;
    const uint32_t bBase = smb + SPLN + (uint32_t)(wn * 64 + laneR) * ROWB + laneC;

    float acc[2][8][4];
#pragma unroll
    for (int i = 0; i < 2; i++)
#pragma unroll
        for (int j = 0; j < 8; j++)
#pragma unroll
            for (int k = 0; k < 4; k++) acc[i][j][k] = 0.f;

    const int T = K / 32;
    {
#pragma unroll
        for (int s = 0; s < 2; s++) {
            CPA16(rowDst + s * 16u,        aP + s * 8);
            CPA16(rowDst + SPLN + s * 16u, bP + s * 8);
        }
        CPCOMMIT();
    }
    if (T > 1) {
#pragma unroll
        for (int s = 0; s < 2; s++) {
            CPA16(rowDst + SSTG + s * 16u,        aP + 32 + s * 8);
            CPA16(rowDst + SSTG + SPLN + s * 16u, bP + 32 + s * 8);
        }
        CPCOMMIT();
    }

    int buf = 0;
    int buf2 = (T > 2) ? 2 : 0;
    for (int t = 0; t < T; ++t) {
        if (t + 2 < T) {
            const int k0 = (t + 2) * 32;
            const uint32_t sb = (uint32_t)buf2 * SSTG;
#pragma unroll
            for (int s = 0; s < 2; s++) {
                CPA16(rowDst + sb + s * 16u,        aP + k0 + s * 8);
                CPA16(rowDst + sb + SPLN + s * 16u, bP + k0 + s * 8);
            }
            CPCOMMIT();
            cpwait<2>();
            if (++buf2 == 3) buf2 = 0;
        } else if (t + 1 < T) {
            cpwait<1>();
        } else {
            cpwait<0>();
        }
        __syncthreads();

        const uint32_t soff = (uint32_t)buf * SSTG;
#pragma unroll
        for (int j = 0; j < 2; j++) {
            const uint32_t ja = soff + (uint32_t)j * 32u;
            uint32_t af[2][4], bf[4][4];
#pragma unroll
            for (int mt = 0; mt < 2; mt++)
                ldm4(af[mt], aBase + ja + (uint32_t)mt * (16u * ROWB));
#pragma unroll
            for (int nt = 0; nt < 4; nt++)
                ldm4(bf[nt], bBase + ja + (uint32_t)nt * (16u * ROWB));
#pragma unroll
            for (int nt = 0; nt < 4; nt++)
#pragma unroll
                for (int mt = 0; mt < 2; mt++) {
                    mma16816(acc[mt][2 * nt],     af[mt], bf[nt][0], bf[nt][2]);
                    mma16816(acc[mt][2 * nt + 1], af[mt], bf[nt][1], bf[nt][3]);
                }
        }
        __syncthreads();
        if (++buf == 3) buf = 0;
    }

    const int lr2 = lane >> 2;
    const int lc2 = (lane & 3) * 2;
#pragma unroll
    for (int mt = 0; mt < 2; mt++) {
#pragma unroll
        for (int h = 0; h < 2; h++) {
            const long m = (long)m0 + wm * 32 + mt * 16 + h * 8 + lr2;
            const long rowb = m * (long)N;
            const __half* erow = (ACT == 3) ? (extra + (long)(m / rowdiv) * N) : nullptr;
#pragma unroll
            for (int nt2 = 0; nt2 < 8; nt2++) {
                const int n = n0 + wn * 64 + nt2 * 8 + lc2;
                float vx = acc[mt][nt2][2 * h]     + bias[n];
                float vy = acc[mt][nt2][2 * h + 1] + bias[n + 1];
                if (ACT == 3) {
                    float2 e = __half22float2(*(const __half2*)(erow + n));
                    vx += e.x; vy += e.y;
                }
                epi_store<ACT>(vx, vy, rowb, n, C);
            }
        }
    }
}

// ---------------- prep / glue kernels ----------------
__global__ void embed_h(const int* __restrict__ drug, const float* __restrict__ emb,
                        __half* __restrict__ x) {
    int idx = blockIdx.x * blockDim.x + threadIdx.x;
    const int total = BATCH * LD * (DIM / 4);
    if (idx >= total) return;
    int d4 = idx & 31;
    int bl = idx >> 5;
    int tok = drug[bl];
    float4 v = ((const float4*)emb)[(size_t)tok * 32 + d4];
    size_t pos = (size_t)bl * 128 + d4 * 4;
    *(__half2*)(x + pos)     = __floats2half2_rn(v.x, v.y);
    *(__half2*)(x + pos + 2) = __floats2half2_rn(v.z, v.w);
}

__global__ void reorder_w_h(const float* __restrict__ w, __half* __restrict__ wr,
                            int O, int Ci, int Kw) {
    int idx = blockIdx.x * blockDim.x + threadIdx.x;
    int total = O * Ci * Kw;
    if (idx >= total) return;
    int o = idx / (Ci * Kw);
    int rr = idx - o * (Ci * Kw);
    int i = rr / Kw;
    int k = rr - i * Kw;
    wr[(size_t)o * Ci * Kw + k * Ci + i] = __float2half_rn(w[idx]);
}

__global__ void midtap_h(const float* __restrict__ w, __half* __restrict__ wr, int total) {
    int idx = blockIdx.x * blockDim.x + threadIdx.x;
    if (idx >= total) return;
    wr[idx] = __float2half_rn(w[idx * 3 + 1]);
}

__global__ void midtap_f32(const float* __restrict__ w, float* __restrict__ wr, int total) {
    int idx = blockIdx.x * blockDim.x + threadIdx.x;
    if (idx >= total) return;
    wr[idx] = w[idx * 3 + 1];
}

__global__ void conv_h(const float* __restrict__ w, __half* __restrict__ wr, int total) {
    int idx = blockIdx.x * blockDim.x + threadIdx.x;
    if (idx >= total) return;
    wr[idx] = __float2half_rn(w[idx]);
}

__global__ void feat1_k(const float* __restrict__ feat, const float* __restrict__ wm,
                        const float* __restrict__ bias, __half* __restrict__ o1) {
    int idx = blockIdx.x * blockDim.x + threadIdx.x;
    if (idx >= BATCH * 128) return;
    int b = idx >> 7, o = idx & 127;
    float s = bias[o];
#pragma unroll
    for (int i = 0; i < 7; i++) s = fmaf(feat[b * 7 + i], wm[o * 7 + i], s);
    o1[idx] = __float2half_rn(fmaxf(s, 0.f));
}

__global__ void reduce_k(const __half* __restrict__ dc, const __half* __restrict__ Am,
                         const __half* __restrict__ fnn,
                         __half* __restrict__ pair) {
    int b = blockIdx.x;
    int c = threadIdx.x;
    const size_t base = (size_t)b * L3O * 512 + c;
    float mx = -1e30f, smv = 0.f;
#pragma unroll 5
    for (int l = 0; l < L3O; l++) {
        float a = __half2float(Am[base + (size_t)l * 512]);
        float d = __half2float(dc[base + (size_t)l * 512]);
        float sg = 1.f / (1.f + expf(-a));
        mx = fmaxf(mx, d * (0.5f + sg));
        smv += a;
    }
    float fsig = 1.f / (1.f + expf(-smv * (1.0f / L3O)));
    float vf = __half2float(fnn[(size_t)b * 512 + c]) * (0.5f + fsig);
    pair[(size_t)b * 1024 + c]       = __float2half_rn(mx);
    pair[(size_t)b * 1024 + 512 + c] = __float2half_rn(vf);
}

__global__ void final_k(const __half* __restrict__ h3, const float* __restrict__ Wo,
                        const float* __restrict__ bo, float* __restrict__ out) {
    int b = blockIdx.x;
    int t = threadIdx.x;
    float s = 0.f;
#pragma unroll
    for (int c = t; c < 512; c += 128)
        s = fmaf(__half2float(h3[(size_t)b * 512 + c]), Wo[c], s);
#pragma unroll
    for (int o = 16; o > 0; o >>= 1) s += __shfl_down_sync(0xffffffffu, s, o);
    __shared__ float red[4];
    if ((t & 31) == 0) red[t >> 5] = s;
    __syncthreads();
    if (t == 0) out[b] = red[0] + red[1] + red[2] + red[3] + bo[0];
}

// ---------------- host launch ----------------
#define GADDR(p, sym) cudaGetSymbolAddress((void**)&p, sym)

extern "C" void kernel_launch(void* const* d_in, const int* in_sizes, int n_in,
                              void* d_out, int out_size) {
    const int*   drug    = (const int*)  d_in[0];
    const float* feature = (const float*)d_in[1];
    const float* emb     = (const float*)d_in[2];
    const float* dw1 = (const float*)d_in[3];  const float* db1 = (const float*)d_in[4];
    const float* dw2 = (const float*)d_in[5];  const float* db2 = (const float*)d_in[6];
    const float* dw3 = (const float*)d_in[7];  const float* db3 = (const float*)d_in[8];
    const float* fw1 = (const float*)d_in[9];  const float* fb1 = (const float*)d_in[10];
    const float* fw2 = (const float*)d_in[11]; const float* fb2 = (const float*)d_in[12];
    const float* fw3 = (const float*)d_in[13]; const float* fb3 = (const float*)d_in[14];
    const float* Wda = (const float*)d_in[15]; const float* bda = (const float*)d_in[16];
    const float* Wfa = (const float*)d_in[17]; const float* bfa = (const float*)d_in[18];
    const float* Watt= (const float*)d_in[19]; const float* batt= (const float*)d_in[20];
    const float* W1  = (const float*)d_in[21]; const float* b1  = (const float*)d_in[22];
    const float* W2  = (const float*)d_in[23]; const float* b2  = (const float*)d_in[24];
    const float* W3  = (const float*)d_in[25]; const float* b3  = (const float*)d_in[26];
    const float* Wo  = (const float*)d_in[27]; const float* bo  = (const float*)d_in[28];
    float* out = (float*)d_out;

    __half *x,*h1,*h2,*dc,*att,*hf1,*hf2,*fnn,*pair,*fh1,*fh2,*Am,*fatt,*fh3;
    __half *w1r,*w2r,*w3r,*fwm2,*fwm3,*WdaH,*WfaH,*WattH,*W1H,*W2H,*W3H;
    float *fwm1;
    GADDR(x, g_x); GADDR(h1, g_h1); GADDR(h2, g_h2);
    GADDR(dc, g_dc); GADDR(att, g_att);
    GADDR(hf1, g_hf1); GADDR(hf2, g_hf2); GADDR(fnn, g_fnn);
    GADDR(pair, g_pair); GADDR(fh1, g_fh1); GADDR(fh2, g_fh2);
    GADDR(Am, g_Am); GADDR(fatt, g_fatt); GADDR(fh3, g_fh3);
    GADDR(w1r, g_w1r); GADDR(w2r, g_w2r); GADDR(w3r, g_w3r);
    GADDR(fwm2, g_fwm2); GADDR(fwm3, g_fwm3);
    GADDR(WdaH, g_Wda); GADDR(WfaH, g_Wfa); GADDR(WattH, g_Watt);
    GADDR(W1H, g_W1); GADDR(W2H, g_W2); GADDR(W3H, g_W3);
    GADDR(fwm1, g_fwm1);

    cudaFuncSetAttribute(gemmW<0>, cudaFuncAttributeMaxDynamicSharedMemorySize, WSMEM);
    cudaFuncSetAttribute(gemmW<1>, cudaFuncAttributeMaxDynamicSharedMemorySize, WSMEM);
    cudaFuncSetAttribute(gemmW<3>, cudaFuncAttributeMaxDynamicSharedMemorySize, WSMEM);
    cudaFuncSetAttribute(gemmS<0>, cudaFuncAttributeMaxDynamicSharedMemorySize, SSMEM);
    cudaFuncSetAttribute(gemmS<1>, cudaFuncAttributeMaxDynamicSharedMemorySize, SSMEM);
    cudaFuncSetAttribute(gemmS<2>, cudaFuncAttributeMaxDynamicSharedMemorySize, SSMEM);

    static cudaStream_t s2 = nullptr;
    static cudaEvent_t evFork = nullptr, evW = nullptr, evJoin = nullptr;
    if (s2 == nullptr) {
        cudaStreamCreateWithFlags(&s2, cudaStreamNonBlocking);
        cudaEventCreateWithFlags(&evFork, cudaEventDisableTiming);
        cudaEventCreateWithFlags(&evW,    cudaEventDisableTiming);
        cudaEventCreateWithFlags(&evJoin, cudaEventDisableTiming);
    }

    // ---- fork ----
    cudaEventRecord(evFork, 0);
    cudaStreamWaitEvent(s2, evFork, 0);

    // ---- stream 0: minimal conv1 prerequisites, then conv chain ----
    embed_h<<<(BATCH * LD * 32 + 255) / 256, 256>>>(drug, emb, x);
    reorder_w_h<<<(128 * 128 * 4 + 255) / 256, 256>>>(dw1, w1r, 128, 128, 4);

    gemmS<1><<<dim3(1, (BATCH * L1O) / 128), 256, SSMEM>>>(x, w1r, db1,
        nullptr, h1, 128, 512, L1O, (long)LD * 128, 128L, 1);

    // ---- stream s2: w2/w3 reorders first (needed by conv2/conv3), then rest ----
    reorder_w_h<<<(256 * 128 * 6 + 255) / 256, 256, 0, s2>>>(dw2, w2r, 256, 128, 6);
    reorder_w_h<<<(512 * 256 * 8 + 255) / 256, 256, 0, s2>>>(dw3, w3r, 512, 256, 8);
    cudaEventRecord(evW, s2);

    midtap_f32<<<(128 * 7 + 255) / 256, 256, 0, s2>>>(fw1, fwm1, 128 * 7);
    midtap_h<<<(256 * 128 + 255) / 256, 256, 0, s2>>>(fw2, fwm2, 256 * 128);
    midtap_h<<<(512 * 256 + 255) / 256, 256, 0, s2>>>(fw3, fwm3, 512 * 256);
    conv_h<<<(512 * 512 + 255) / 256, 256, 0, s2>>>(Wda, WdaH, 512 * 512);
    conv_h<<<(512 * 512 + 255) / 256, 256, 0, s2>>>(Wfa, WfaH, 512 * 512);
    conv_h<<<(512 * 512 + 255) / 256, 256, 0, s2>>>(Watt, WattH, 512 * 512);
    conv_h<<<(1024 * 1024 + 255) / 256, 256, 0, s2>>>(W1, W1H, 1024 * 1024);
    conv_h<<<(1024 * 1024 + 255) / 256, 256, 0, s2>>>(W2, W2H, 1024 * 1024);
    conv_h<<<(512 * 1024 + 255) / 256, 256, 0, s2>>>(W3, W3H, 512 * 1024);

    feat1_k<<<(BATCH * 128) / 256, 256, 0, s2>>>(feature, fwm1, fb1, hf1);
    gemmS<1><<<dim3(2, BATCH / 128), 256, SSMEM, s2>>>(hf1, fwm2, fb2,
        nullptr, hf2, 256, 128, BATCH, 0L, 128L, 1);
    gemmS<1><<<dim3(4, BATCH / 128), 256, SSMEM, s2>>>(hf2, fwm3, fb3,
        nullptr, fnn, 512, 256, BATCH, 0L, 256L, 1);
    gemmS<0><<<dim3(4, BATCH / 128), 256, SSMEM, s2>>>(fnn, WfaH, bfa,
        nullptr, fatt, 512, 512, BATCH, 0L, 512L, 1);
    cudaEventRecord(evJoin, s2);

    // ---- stream 0: conv2/conv3 (need w2r/w3r from s2) ----
    cudaStreamWaitEvent(0, evW, 0);
    gemmW<1><<<dim3(1, (BATCH * L2O) / 128), 256, WSMEM>>>(h1, w2r, db2,
        nullptr, h2, 256, 768, L2O, (long)L1O * 128, 128L, 1);
    gemmW<1><<<dim3(2, (BATCH * L3O) / 128), 256, WSMEM>>>(h2, w3r, db3,
        nullptr, dc, 512, 2048, L3O, (long)L2O * 256, 256L, 1);

    // ---- join: att chain needs fatt/WdaH/WattH; FC needs W1H..W3H ----
    cudaStreamWaitEvent(0, evJoin, 0);

    gemmW<3><<<dim3(2, (BATCH * L3O) / 128), 256, WSMEM>>>(dc, WdaH, bda,
        fatt, att, 512, 512, BATCH * L3O, 0L, 512L, L3O);
    gemmW<0><<<dim3(2, (BATCH * L3O) / 128), 256, WSMEM>>>(att, WattH, batt,
        nullptr, Am, 512, 512, BATCH * L3O, 0L, 512L, 1);

    reduce_k<<<BATCH, 512>>>(dc, Am, fnn, pair);

    gemmS<2><<<dim3(8, BATCH / 128), 256, SSMEM>>>(pair, W1H, b1,
        nullptr, fh1, 1024, 1024, BATCH, 0L, 1024L, 1);
    gemmS<2><<<dim3(8, BATCH / 128), 256, SSMEM>>>(fh1, W2H, b2,
        nullptr, fh2, 1024, 1024, BATCH, 0L, 1024L, 1);
    gemmS<2><<<dim3(4, BATCH / 128), 256, SSMEM>>>(fh2, W3H, b3,
        nullptr, fh3, 512, 1024, BATCH, 0L, 1024L, 1);

    final_k<<<BATCH, 128>>>(fh3, Wo, bo, out);
}